// round 6
// baseline (speedup 1.0000x reference)
#include <cuda_runtime.h>
#include <cstdint>
#include <cstddef>

// RT-DETR v2 deformable attention. B=32 Q=300 d=256 H=8 C=32 S=8400 P=12
// S1: value = enc@W_val+b  (int8 IMMA 3-split, inline A-quant) -> (B,H,S,C)
// S2a: proj = hidden@[W_off|W_attn|pad320]  (fp32 sgemm64)
// S2b: softmax + bilinear sampling (warp per head)
// S3: out = mixed@W_out+b (fp32 sgemm64)

#define B_SZ 32
#define Q_SZ 300
#define H_SZ 8
#define C_SZ 32
#define S_SZ 8400
#define P_SZ 12
#define KA   (8.0f / 127.0f)

__device__ float  g_value[(size_t)B_SZ * H_SZ * S_SZ * C_SZ];
__device__ float  g_mixed[(size_t)B_SZ * Q_SZ * 256];
__device__ float  g_proj[(size_t)B_SZ * Q_SZ * 320];
__device__ int8_t g_bq1[256 * 256];
__device__ int8_t g_bq2[256 * 256];
__device__ float  g_bscale[256];
__device__ float  g_wproj[256 * 320];
__device__ float  g_bproj[320];

// ---------------- quant helpers ----------------
__device__ __forceinline__ void qsplit(float xs, int& o1, int& o2) {
    float q1f = rintf(xs);
    q1f = fminf(127.f, fmaxf(-127.f, q1f));
    float q2f = rintf((xs - q1f) * 254.f);
    q2f = fminf(127.f, fmaxf(-127.f, q2f));
    o1 = (int)q1f; o2 = (int)q2f;
}
__device__ __forceinline__ void q4pack(float4 v, float inv_s,
                                       uint32_t& p1, uint32_t& p2) {
    int a1, a2, b1, b2, c1, c2, d1, d2;
    qsplit(v.x * inv_s, a1, a2);
    qsplit(v.y * inv_s, b1, b2);
    qsplit(v.z * inv_s, c1, c2);
    qsplit(v.w * inv_s, d1, d2);
    p1 = (a1 & 0xff) | ((b1 & 0xff) << 8) | ((c1 & 0xff) << 16) | (d1 << 24);
    p2 = (a2 & 0xff) | ((b2 & 0xff) << 8) | ((c2 & 0xff) << 16) | (d2 << 24);
}

// ---------------- weight preps ----------------
__global__ void bprep_k(const float* __restrict__ W, int8_t* __restrict__ bq1,
                        int8_t* __restrict__ bq2, float* __restrict__ bscale)
{
    __shared__ float red[256];
    const int n = blockIdx.x, k = threadIdx.x;
    const float w = W[(size_t)k * 256 + n];
    red[k] = fabsf(w);
    __syncthreads();
    for (int s = 128; s; s >>= 1) {
        if (k < s) red[k] = fmaxf(red[k], red[k + s]);
        __syncthreads();
    }
    float s = red[0] / 127.f;
    if (s == 0.f) s = 1.f;
    int q1, q2;
    qsplit(w / s, q1, q2);
    bq1[n * 256 + k] = (int8_t)q1;
    bq2[n * 256 + k] = (int8_t)q2;
    if (k == 0) bscale[n] = s;
}

__global__ void pprep_k(const float* __restrict__ W_off,
                        const float* __restrict__ b_off,
                        const float* __restrict__ W_attn,
                        const float* __restrict__ b_attn,
                        float* __restrict__ wp, float* __restrict__ bp)
{
    const int k = blockIdx.x, j = threadIdx.x;
    float v = 0.f, bv = 0.f;
    if (j < 192)      { v = W_off[(size_t)k * 192 + j];         bv = b_off[j]; }
    else if (j < 288) { v = W_attn[(size_t)k * 96 + (j - 192)]; bv = b_attn[j - 192]; }
    wp[(size_t)k * 320 + j] = v;
    if (k == 0) bp[j] = bv;
}

// ---------------- Stage 1: IMMA GEMM ----------------
__device__ __forceinline__ void imma16832(int* d, const uint32_t* a,
                                          const uint32_t* b) {
    asm volatile(
        "mma.sync.aligned.m16n8k32.row.col.s32.s8.s8.s32 "
        "{%0,%1,%2,%3}, {%4,%5,%6,%7}, {%8,%9}, {%0,%1,%2,%3};"
        : "+r"(d[0]), "+r"(d[1]), "+r"(d[2]), "+r"(d[3])
        : "r"(a[0]), "r"(a[1]), "r"(a[2]), "r"(a[3]), "r"(b[0]), "r"(b[1]));
}

// Tile 128x64, K-chunks 32, double-buffered, 8 warps (4m x 2n of 32x32).
__global__ __launch_bounds__(256) void gemm_imma_k(
    const float* __restrict__ A,
    const int8_t* __restrict__ Bq1, const int8_t* __restrict__ Bq2,
    const float* __restrict__ bscale, const float* __restrict__ bias,
    float* __restrict__ C)
{
    __shared__ int8_t sA[2][2][128 * 48];
    __shared__ int8_t sB[2][2][64 * 48];

    const int tid = threadIdx.x;
    const int wid = tid >> 5, lane = tid & 31;
    const int m0 = blockIdx.y * 128, n0 = blockIdx.x * 64;
    const int wm = wid & 3, wn = wid >> 2;
    const int lr = lane >> 2, lc4 = (lane & 3) * 4;

    // loaders: A fp32 -> quant; 4 float4/thread/chunk. B int8 uint2/thread.
    int arow[4], acol[4];
    #pragma unroll
    for (int i = 0; i < 4; i++) {
        const int idx = tid + i * 256;
        arow[i] = idx >> 3;
        acol[i] = (idx & 7) * 4;
    }
    const int br = tid >> 2, bc = (tid & 3) * 8;
    const int8_t* gB1 = Bq1 + (size_t)(n0 + br) * 256 + bc;
    const int8_t* gB2 = Bq2 + (size_t)(n0 + br) * 256 + bc;

    int acc1[2][4][4] = {}, acc2[2][4][4] = {};
    float4 pa[4];
    uint2 pb1, pb2;

    #pragma unroll
    for (int i = 0; i < 4; i++)
        pa[i] = *reinterpret_cast<const float4*>(&A[(size_t)(m0 + arow[i]) * 256 + acol[i]]);
    pb1 = *reinterpret_cast<const uint2*>(gB1);
    pb2 = *reinterpret_cast<const uint2*>(gB2);

#define STORE_I8(BUF) do {                                                     \
    _Pragma("unroll")                                                          \
    for (int i = 0; i < 4; i++) {                                              \
        uint32_t p1, p2;                                                       \
        q4pack(pa[i], 1.f / KA, p1, p2);                                       \
        *reinterpret_cast<uint32_t*>(&sA[BUF][0][arow[i] * 48 + acol[i]]) = p1; \
        *reinterpret_cast<uint32_t*>(&sA[BUF][1][arow[i] * 48 + acol[i]]) = p2; \
    }                                                                          \
    *reinterpret_cast<uint2*>(&sB[BUF][0][br * 48 + bc]) = pb1;                \
    *reinterpret_cast<uint2*>(&sB[BUF][1][br * 48 + bc]) = pb2;                \
} while (0)

    STORE_I8(0);
    __syncthreads();

    #pragma unroll 1
    for (int c = 0; c < 8; c++) {
        const int buf = c & 1;
        if (c < 7) {
            const int k0 = (c + 1) * 32;
            #pragma unroll
            for (int i = 0; i < 4; i++)
                pa[i] = *reinterpret_cast<const float4*>(
                    &A[(size_t)(m0 + arow[i]) * 256 + k0 + acol[i]]);
            pb1 = *reinterpret_cast<const uint2*>(gB1 + k0);
            pb2 = *reinterpret_cast<const uint2*>(gB2 + k0);
        }

        uint32_t a1[2][4], a2[2][4], b1[4][2], b2[4][2];
        #pragma unroll
        for (int mt = 0; mt < 2; mt++) {
            const int r = wm * 32 + mt * 16 + lr;
            a1[mt][0] = *reinterpret_cast<const uint32_t*>(&sA[buf][0][r * 48 + lc4]);
            a1[mt][1] = *reinterpret_cast<const uint32_t*>(&sA[buf][0][(r + 8) * 48 + lc4]);
            a1[mt][2] = *reinterpret_cast<const uint32_t*>(&sA[buf][0][r * 48 + lc4 + 16]);
            a1[mt][3] = *reinterpret_cast<const uint32_t*>(&sA[buf][0][(r + 8) * 48 + lc4 + 16]);
            a2[mt][0] = *reinterpret_cast<const uint32_t*>(&sA[buf][1][r * 48 + lc4]);
            a2[mt][1] = *reinterpret_cast<const uint32_t*>(&sA[buf][1][(r + 8) * 48 + lc4]);
            a2[mt][2] = *reinterpret_cast<const uint32_t*>(&sA[buf][1][r * 48 + lc4 + 16]);
            a2[mt][3] = *reinterpret_cast<const uint32_t*>(&sA[buf][1][(r + 8) * 48 + lc4 + 16]);
        }
        #pragma unroll
        for (int nt = 0; nt < 4; nt++) {
            const int n = wn * 32 + nt * 8 + lr;
            b1[nt][0] = *reinterpret_cast<const uint32_t*>(&sB[buf][0][n * 48 + lc4]);
            b1[nt][1] = *reinterpret_cast<const uint32_t*>(&sB[buf][0][n * 48 + lc4 + 16]);
            b2[nt][0] = *reinterpret_cast<const uint32_t*>(&sB[buf][1][n * 48 + lc4]);
            b2[nt][1] = *reinterpret_cast<const uint32_t*>(&sB[buf][1][n * 48 + lc4 + 16]);
        }

        #pragma unroll
        for (int mt = 0; mt < 2; mt++)
            #pragma unroll
            for (int nt = 0; nt < 4; nt++) {
                imma16832(acc1[mt][nt], a1[mt], b1[nt]);
                imma16832(acc2[mt][nt], a1[mt], b2[nt]);
                imma16832(acc2[mt][nt], a2[mt], b1[nt]);
            }

        if (c < 7) {
            STORE_I8(buf ^ 1);
            __syncthreads();
        }
    }
#undef STORE_I8

    // epilogue: v = KA*sB[n]*(acc1 + acc2/254) + bias; permuted (B,H,S,C)
    #pragma unroll
    for (int nt = 0; nt < 4; nt++) {
        const int n = n0 + wn * 32 + nt * 8 + (lane & 3) * 2;
        const float s0 = KA * bscale[n], s1 = KA * bscale[n + 1];
        const float bi0 = bias[n], bi1 = bias[n + 1];
        const int hh = n >> 5, cc = n & 31;
        #pragma unroll
        for (int mt = 0; mt < 2; mt++) {
            const int mA = m0 + wm * 32 + mt * 16 + lr;
            const int mB = mA + 8;
            const int bbA = mA / S_SZ, ssA = mA % S_SZ;
            const int bbB = mB / S_SZ, ssB = mB % S_SZ;
            float2 v0, v1;
            v0.x = s0 * ((float)acc1[mt][nt][0] + (float)acc2[mt][nt][0] * (1.f / 254.f)) + bi0;
            v0.y = s1 * ((float)acc1[mt][nt][1] + (float)acc2[mt][nt][1] * (1.f / 254.f)) + bi1;
            v1.x = s0 * ((float)acc1[mt][nt][2] + (float)acc2[mt][nt][2] * (1.f / 254.f)) + bi0;
            v1.y = s1 * ((float)acc1[mt][nt][3] + (float)acc2[mt][nt][3] * (1.f / 254.f)) + bi1;
            *reinterpret_cast<float2*>(
                &C[(((size_t)(bbA * H_SZ + hh)) * S_SZ + ssA) * C_SZ + cc]) = v0;
            *reinterpret_cast<float2*>(
                &C[(((size_t)(bbB * H_SZ + hh)) * S_SZ + ssB) * C_SZ + cc]) = v1;
        }
    }
}

// ---------------- fp32 SGEMM 64x64 ----------------
__global__ __launch_bounds__(256) void sgemm64_k(
    const float* __restrict__ A, const float* __restrict__ Bm,
    const float* __restrict__ bias, float* __restrict__ C, int N)
{
    __shared__ float As[16][68];
    __shared__ float Bs[16][68];

    const int tid = threadIdx.x;
    const int m0 = blockIdx.y * 64, n0 = blockIdx.x * 64;
    const int ty = tid >> 4, tx = tid & 15;
    const int arow = tid >> 2, akq = tid & 3;
    const int bkk = tid >> 4, bnq = tid & 15;

    float acc[4][4] = {};

    for (int k0 = 0; k0 < 256; k0 += 16) {
        float4 av = *reinterpret_cast<const float4*>(
            &A[(size_t)(m0 + arow) * 256 + k0 + akq * 4]);
        As[akq * 4 + 0][arow] = av.x;
        As[akq * 4 + 1][arow] = av.y;
        As[akq * 4 + 2][arow] = av.z;
        As[akq * 4 + 3][arow] = av.w;
        *reinterpret_cast<float4*>(&Bs[bkk][bnq * 4]) =
            *reinterpret_cast<const float4*>(&Bm[(size_t)(k0 + bkk) * N + n0 + bnq * 4]);
        __syncthreads();
        #pragma unroll
        for (int kk = 0; kk < 16; kk++) {
            float4 ra = *reinterpret_cast<const float4*>(&As[kk][ty * 4]);
            float4 rb = *reinterpret_cast<const float4*>(&Bs[kk][tx * 4]);
            float a_[4] = {ra.x, ra.y, ra.z, ra.w};
            float b_[4] = {rb.x, rb.y, rb.z, rb.w};
            #pragma unroll
            for (int i = 0; i < 4; i++)
                #pragma unroll
                for (int j = 0; j < 4; j++)
                    acc[i][j] += a_[i] * b_[j];
        }
        __syncthreads();
    }

    #pragma unroll
    for (int i = 0; i < 4; i++) {
        const int m = m0 + ty * 4 + i;
        const int n = n0 + tx * 4;
        float4 v;
        v.x = acc[i][0] + bias[n + 0];
        v.y = acc[i][1] + bias[n + 1];
        v.z = acc[i][2] + bias[n + 2];
        v.w = acc[i][3] + bias[n + 3];
        *reinterpret_cast<float4*>(&C[(size_t)m * N + n]) = v;
    }
}

// ---------------- Stage 2b: sampling ----------------
__global__ __launch_bounds__(256) void sample_k(
    const float* __restrict__ proj, const float* __restrict__ refp,
    const float* __restrict__ value, float* __restrict__ mixed)
{
    const int blk = blockIdx.x;        // b*Q + q
    const int b = blk / Q_SZ;
    const int h = threadIdx.x >> 5;
    const int lane = threadIdx.x & 31;

    const float rx = __ldg(&refp[blk * 4 + 0]);
    const float ry = __ldg(&refp[blk * 4 + 1]);
    const float rw = __ldg(&refp[blk * 4 + 2]);
    const float rh = __ldg(&refp[blk * 4 + 3]);

    float gx = 0.f, gy = 0.f, logit = -1e30f;
    if (lane < P_SZ) {
        const float ox = __ldg(&proj[(size_t)blk * 320 + (h * P_SZ + lane) * 2]);
        const float oy = __ldg(&proj[(size_t)blk * 320 + (h * P_SZ + lane) * 2 + 1]);
        logit = __ldg(&proj[(size_t)blk * 320 + 192 + h * P_SZ + lane]);
        const float Wf = (lane < 4) ? 80.f : ((lane < 8) ? 40.f : 20.f);
        gx = (rx + ox * rw * 0.125f) * Wf - 0.5f;
        gy = (ry + oy * rh * 0.125f) * Wf - 0.5f;
    }
    float mx = logit;
    #pragma unroll
    for (int o = 16; o; o >>= 1) mx = fmaxf(mx, __shfl_xor_sync(0xffffffffu, mx, o));
    const float e = (lane < P_SZ) ? __expf(logit - mx) : 0.f;
    float sm = e;
    #pragma unroll
    for (int o = 16; o; o >>= 1) sm += __shfl_xor_sync(0xffffffffu, sm, o);
    const float w = e / sm;

    const float* vb = value + ((size_t)(b * H_SZ + h) * S_SZ) * C_SZ + lane;
    float acc = 0.f;
    #pragma unroll
    for (int p = 0; p < P_SZ; p++) {
        const float gxp = __shfl_sync(0xffffffffu, gx, p);
        const float gyp = __shfl_sync(0xffffffffu, gy, p);
        const float wp  = __shfl_sync(0xffffffffu, w,  p);
        const int Wl = (p < 4) ? 80 : ((p < 8) ? 40 : 20);
        const int st = (p < 4) ? 0 : ((p < 8) ? 6400 : 8000);
        const float x0f = floorf(gxp), y0f = floorf(gyp);
        const float wx1 = gxp - x0f, wx0 = 1.f - wx1;
        const float wy1 = gyp - y0f, wy0 = 1.f - wy1;
        const int x0 = (int)x0f, y0 = (int)y0f, x1 = x0 + 1, y1 = y0 + 1;
        const bool xv0 = (x0 >= 0) && (x0 < Wl);
        const bool xv1 = (x1 >= 0) && (x1 < Wl);
        const bool yv0 = (y0 >= 0) && (y0 < Wl);
        const bool yv1 = (y1 >= 0) && (y1 < Wl);
        const float* lv = vb + (size_t)st * C_SZ;
        float s = 0.f;
        if (xv0 && yv0) s += wx0 * wy0 * lv[(size_t)(y0 * Wl + x0) * C_SZ];
        if (xv1 && yv0) s += wx1 * wy0 * lv[(size_t)(y0 * Wl + x1) * C_SZ];
        if (xv0 && yv1) s += wx0 * wy1 * lv[(size_t)(y1 * Wl + x0) * C_SZ];
        if (xv1 && yv1) s += wx1 * wy1 * lv[(size_t)(y1 * Wl + x1) * C_SZ];
        acc += wp * s;
    }
    mixed[(size_t)blk * 256 + h * C_SZ + lane] = acc;
}

// ---------------------------------------------------------------------------
extern "C" void kernel_launch(void* const* d_in, const int* in_sizes, int n_in,
                              void* d_out, int out_size)
{
    const float* hidden = (const float*)d_in[0];
    const float* enc    = (const float*)d_in[1];
    const float* refp   = (const float*)d_in[2];
    const float* W_off  = (const float*)d_in[3];
    const float* b_off  = (const float*)d_in[4];
    const float* W_attn = (const float*)d_in[5];
    const float* b_attn = (const float*)d_in[6];
    const float* W_val  = (const float*)d_in[7];
    const float* b_val  = (const float*)d_in[8];
    const float* W_out  = (const float*)d_in[9];
    const float* b_out  = (const float*)d_in[10];
    float* out = (float*)d_out;

    float *value, *mixed, *proj, *bscale, *wproj, *bproj;
    int8_t *bq1, *bq2;
    cudaGetSymbolAddress((void**)&value,  g_value);
    cudaGetSymbolAddress((void**)&mixed,  g_mixed);
    cudaGetSymbolAddress((void**)&proj,   g_proj);
    cudaGetSymbolAddress((void**)&bq1,    g_bq1);
    cudaGetSymbolAddress((void**)&bq2,    g_bq2);
    cudaGetSymbolAddress((void**)&bscale, g_bscale);
    cudaGetSymbolAddress((void**)&wproj,  g_wproj);
    cudaGetSymbolAddress((void**)&bproj,  g_bproj);

    const int M1 = B_SZ * S_SZ;   // 268800
    const int M2 = B_SZ * Q_SZ;   // 9600

    bprep_k<<<256, 256>>>(W_val, bq1, bq2, bscale);
    pprep_k<<<256, 320>>>(W_off, b_off, W_attn, b_attn, wproj, bproj);

    // Stage 1: value projection (IMMA), x-fastest grid for L2 A reuse
    {
        dim3 grid(4, M1 / 128);   // (4, 2100)
        gemm_imma_k<<<grid, 256>>>(enc, bq1, bq2, bscale, b_val, value);
    }
    // Stage 2a: offset/attn projection
    {
        dim3 grid(5, M2 / 64);    // (5, 150)
        sgemm64_k<<<grid, 256>>>(hidden, wproj, bproj, proj, 320);
    }
    // Stage 2b: sampling
    sample_k<<<M2, 256>>>(proj, refp, value, mixed);

    // Stage 3: output projection
    {
        dim3 grid(4, M2 / 64);    // (4, 150)
        sgemm64_k<<<grid, 256>>>(mixed, W_out, b_out, out, 256);
    }
}

// round 7
// speedup vs baseline: 2.2465x; 2.2465x over previous
#include <cuda_runtime.h>
#include <cuda_fp16.h>
#include <cstdint>
#include <cstddef>

// RT-DETR v2 deformable attention. B=32 Q=300 d=256 H=8 C=32 S=8400 P=12
// S1: value = enc@W_val+b  (fp16 HMMA single-term) -> (B,H,S,C)
// S2a: proj = hidden@[W_off|W_attn|pad320]  (fp32 sgemm64)
// S2b: softmax + bilinear sampling (warp per head)
// S3: out = mixed@W_out+b (fp32 sgemm64)

#define B_SZ 32
#define Q_SZ 300
#define H_SZ 8
#define C_SZ 32
#define S_SZ 8400
#define P_SZ 12

__device__ float  g_value[(size_t)B_SZ * H_SZ * S_SZ * C_SZ];   // 275 MB
__device__ float  g_mixed[(size_t)B_SZ * Q_SZ * 256];
__device__ float  g_proj[(size_t)B_SZ * Q_SZ * 320];
__device__ __half g_wh[256 * 256];                               // W_val^T fp16
__device__ float  g_wproj[256 * 320];
__device__ float  g_bproj[320];

// ---------------- weight preps ----------------
__global__ void wprep_k(const float* __restrict__ W, __half* __restrict__ wh)
{
    const int n = blockIdx.x, k = threadIdx.x;
    wh[(size_t)n * 256 + k] = __float2half_rn(W[(size_t)k * 256 + n]);
}

__global__ void pprep_k(const float* __restrict__ W_off,
                        const float* __restrict__ b_off,
                        const float* __restrict__ W_attn,
                        const float* __restrict__ b_attn,
                        float* __restrict__ wp, float* __restrict__ bp)
{
    const int k = blockIdx.x, j = threadIdx.x;
    float v = 0.f, bv = 0.f;
    if (j < 192)      { v = W_off[(size_t)k * 192 + j];         bv = b_off[j]; }
    else if (j < 288) { v = W_attn[(size_t)k * 96 + (j - 192)]; bv = b_attn[j - 192]; }
    wp[(size_t)k * 320 + j] = v;
    if (k == 0) bp[j] = bv;
}

// ---------------- Stage 1: fp16 HMMA GEMM ----------------
__device__ __forceinline__ uint32_t pkhf(float x, float y) {
    __half2 t = __floats2half2_rn(x, y);
    return *reinterpret_cast<uint32_t*>(&t);
}
__device__ __forceinline__ void mma16816(float* d, const uint32_t* a,
                                         const uint32_t* b) {
    asm volatile(
        "mma.sync.aligned.m16n8k16.row.col.f32.f16.f16.f32 "
        "{%0,%1,%2,%3}, {%4,%5,%6,%7}, {%8,%9}, {%0,%1,%2,%3};"
        : "+f"(d[0]), "+f"(d[1]), "+f"(d[2]), "+f"(d[3])
        : "r"(a[0]), "r"(a[1]), "r"(a[2]), "r"(a[3]), "r"(b[0]), "r"(b[1]));
}

#define PITCH 18   // fp16 elems per smem row (16 data + 2 pad)

// C[M,256] = A[M,256] * W^T + bias, permuted store to (B,H,S,C).
// 128x128 tile, 256 threads (8 warps of 32x64), K-chunks 16, double-buffered.
__global__ __launch_bounds__(256) void gemm_hmma_k(
    const float* __restrict__ A, const __half* __restrict__ Wh,
    const float* __restrict__ bias, float* __restrict__ C)
{
    __shared__ uint16_t sA[2][128 * PITCH];
    __shared__ uint16_t sB[2][128 * PITCH];

    const int tid  = threadIdx.x;
    const int wid  = tid >> 5;
    const int lane = tid & 31;
    const int m0 = blockIdx.y * 128;
    const int n0 = blockIdx.x * 128;

    const int m0w = (wid & 3) * 32;   // 4 M-groups of 32
    const int n0w = (wid >> 2) * 64;  // 2 N-groups of 64

    // loaders
    const int arow0 = tid >> 2,          ac0 = (tid & 3) * 4;
    const int arow1 = (tid + 256) >> 2,  ac1 = ((tid + 256) & 3) * 4;
    const int brow  = tid >> 1,          boff = (tid & 1) * 8;

    float acc[2][8][4] = {};
    float4 pa0, pa1;
    uint4  pbh;

    pa0 = *reinterpret_cast<const float4*>(&A[(size_t)(m0 + arow0) * 256 + ac0]);
    pa1 = *reinterpret_cast<const float4*>(&A[(size_t)(m0 + arow1) * 256 + ac1]);
    pbh = *reinterpret_cast<const uint4*>(&Wh[(size_t)(n0 + brow) * 256 + boff]);

#define STORE_CHUNK(BUF) do {                                              \
    {   uint16_t* p = &sA[BUF][arow0 * PITCH + ac0];                       \
        *reinterpret_cast<uint32_t*>(p)     = pkhf(pa0.x, pa0.y);          \
        *reinterpret_cast<uint32_t*>(p + 2) = pkhf(pa0.z, pa0.w);          \
    }                                                                      \
    {   uint16_t* p = &sA[BUF][arow1 * PITCH + ac1];                       \
        *reinterpret_cast<uint32_t*>(p)     = pkhf(pa1.x, pa1.y);          \
        *reinterpret_cast<uint32_t*>(p + 2) = pkhf(pa1.z, pa1.w);          \
    }                                                                      \
    {   uint16_t* p = &sB[BUF][brow * PITCH + boff];                       \
        *reinterpret_cast<uint32_t*>(p)     = pbh.x;                       \
        *reinterpret_cast<uint32_t*>(p + 2) = pbh.y;                       \
        *reinterpret_cast<uint32_t*>(p + 4) = pbh.z;                       \
        *reinterpret_cast<uint32_t*>(p + 6) = pbh.w;                       \
    }                                                                      \
} while (0)

    STORE_CHUNK(0);
    __syncthreads();

    const int lr  = lane >> 2;
    const int lc2 = (lane & 3) * 2;

    #pragma unroll 1
    for (int c = 0; c < 16; ++c) {
        const int buf = c & 1;
        if (c < 15) {
            const int k0 = (c + 1) * 16;
            pa0 = *reinterpret_cast<const float4*>(&A[(size_t)(m0 + arow0) * 256 + k0 + ac0]);
            pa1 = *reinterpret_cast<const float4*>(&A[(size_t)(m0 + arow1) * 256 + k0 + ac1]);
            pbh = *reinterpret_cast<const uint4*>(&Wh[(size_t)(n0 + brow) * 256 + k0 + boff]);
        }

        uint32_t ah[2][4], bh[8][2];
        #pragma unroll
        for (int mt = 0; mt < 2; mt++) {
            const int r = m0w + mt * 16 + lr;
            ah[mt][0] = *reinterpret_cast<const uint32_t*>(&sA[buf][r * PITCH + lc2]);
            ah[mt][1] = *reinterpret_cast<const uint32_t*>(&sA[buf][(r + 8) * PITCH + lc2]);
            ah[mt][2] = *reinterpret_cast<const uint32_t*>(&sA[buf][r * PITCH + lc2 + 8]);
            ah[mt][3] = *reinterpret_cast<const uint32_t*>(&sA[buf][(r + 8) * PITCH + lc2 + 8]);
        }
        #pragma unroll
        for (int nt = 0; nt < 8; nt++) {
            const int r = n0w + nt * 8 + lr;
            bh[nt][0] = *reinterpret_cast<const uint32_t*>(&sB[buf][r * PITCH + lc2]);
            bh[nt][1] = *reinterpret_cast<const uint32_t*>(&sB[buf][r * PITCH + lc2 + 8]);
        }

        #pragma unroll
        for (int mt = 0; mt < 2; mt++)
            #pragma unroll
            for (int nt = 0; nt < 8; nt++)
                mma16816(acc[mt][nt], ah[mt], bh[nt]);

        if (c < 15) {
            STORE_CHUNK(buf ^ 1);
            __syncthreads();
        }
    }
#undef STORE_CHUNK

    // epilogue: permuted store (B,H,S,C) with bias
    #pragma unroll
    for (int mt = 0; mt < 2; mt++) {
        const int mA = m0 + m0w + mt * 16 + lr;
        const int mB = mA + 8;
        const int bbA = mA / S_SZ, ssA = mA % S_SZ;
        const int bbB = mB / S_SZ, ssB = mB % S_SZ;
        #pragma unroll
        for (int nt = 0; nt < 8; nt++) {
            const int n = n0 + n0w + nt * 8 + lc2;
            const int h = n >> 5, cc = n & 31;
            const float bi0 = bias[n], bi1 = bias[n + 1];
            float2 v0, v1;
            v0.x = acc[mt][nt][0] + bi0;
            v0.y = acc[mt][nt][1] + bi1;
            v1.x = acc[mt][nt][2] + bi0;
            v1.y = acc[mt][nt][3] + bi1;
            *reinterpret_cast<float2*>(
                &C[(((size_t)(bbA * H_SZ + h)) * S_SZ + ssA) * C_SZ + cc]) = v0;
            *reinterpret_cast<float2*>(
                &C[(((size_t)(bbB * H_SZ + h)) * S_SZ + ssB) * C_SZ + cc]) = v1;
        }
    }
}

// ---------------- fp32 SGEMM 64x64 ----------------
__global__ __launch_bounds__(256) void sgemm64_k(
    const float* __restrict__ A, const float* __restrict__ Bm,
    const float* __restrict__ bias, float* __restrict__ C, int N)
{
    __shared__ float As[16][68];
    __shared__ float Bs[16][68];

    const int tid = threadIdx.x;
    const int m0 = blockIdx.y * 64, n0 = blockIdx.x * 64;
    const int ty = tid >> 4, tx = tid & 15;
    const int arow = tid >> 2, akq = tid & 3;
    const int bkk = tid >> 4, bnq = tid & 15;

    float acc[4][4] = {};

    for (int k0 = 0; k0 < 256; k0 += 16) {
        float4 av = *reinterpret_cast<const float4*>(
            &A[(size_t)(m0 + arow) * 256 + k0 + akq * 4]);
        As[akq * 4 + 0][arow] = av.x;
        As[akq * 4 + 1][arow] = av.y;
        As[akq * 4 + 2][arow] = av.z;
        As[akq * 4 + 3][arow] = av.w;
        *reinterpret_cast<float4*>(&Bs[bkk][bnq * 4]) =
            *reinterpret_cast<const float4*>(&Bm[(size_t)(k0 + bkk) * N + n0 + bnq * 4]);
        __syncthreads();
        #pragma unroll
        for (int kk = 0; kk < 16; kk++) {
            float4 ra = *reinterpret_cast<const float4*>(&As[kk][ty * 4]);
            float4 rb = *reinterpret_cast<const float4*>(&Bs[kk][tx * 4]);
            float a_[4] = {ra.x, ra.y, ra.z, ra.w};
            float b_[4] = {rb.x, rb.y, rb.z, rb.w};
            #pragma unroll
            for (int i = 0; i < 4; i++)
                #pragma unroll
                for (int j = 0; j < 4; j++)
                    acc[i][j] += a_[i] * b_[j];
        }
        __syncthreads();
    }

    #pragma unroll
    for (int i = 0; i < 4; i++) {
        const int m = m0 + ty * 4 + i;
        const int n = n0 + tx * 4;
        float4 v;
        v.x = acc[i][0] + bias[n + 0];
        v.y = acc[i][1] + bias[n + 1];
        v.z = acc[i][2] + bias[n + 2];
        v.w = acc[i][3] + bias[n + 3];
        *reinterpret_cast<float4*>(&C[(size_t)m * N + n]) = v;
    }
}

// ---------------- Stage 2b: sampling ----------------
__global__ __launch_bounds__(256) void sample_k(
    const float* __restrict__ proj, const float* __restrict__ refp,
    const float* __restrict__ value, float* __restrict__ mixed)
{
    const int blk = blockIdx.x;        // b*Q + q
    const int b = blk / Q_SZ;
    const int h = threadIdx.x >> 5;
    const int lane = threadIdx.x & 31;

    const float rx = __ldg(&refp[blk * 4 + 0]);
    const float ry = __ldg(&refp[blk * 4 + 1]);
    const float rw = __ldg(&refp[blk * 4 + 2]);
    const float rh = __ldg(&refp[blk * 4 + 3]);

    float gx = 0.f, gy = 0.f, logit = -1e30f;
    if (lane < P_SZ) {
        const float ox = __ldg(&proj[(size_t)blk * 320 + (h * P_SZ + lane) * 2]);
        const float oy = __ldg(&proj[(size_t)blk * 320 + (h * P_SZ + lane) * 2 + 1]);
        logit = __ldg(&proj[(size_t)blk * 320 + 192 + h * P_SZ + lane]);
        const float Wf = (lane < 4) ? 80.f : ((lane < 8) ? 40.f : 20.f);
        gx = (rx + ox * rw * 0.125f) * Wf - 0.5f;
        gy = (ry + oy * rh * 0.125f) * Wf - 0.5f;
    }
    float mx = logit;
    #pragma unroll
    for (int o = 16; o; o >>= 1) mx = fmaxf(mx, __shfl_xor_sync(0xffffffffu, mx, o));
    const float e = (lane < P_SZ) ? __expf(logit - mx) : 0.f;
    float sm = e;
    #pragma unroll
    for (int o = 16; o; o >>= 1) sm += __shfl_xor_sync(0xffffffffu, sm, o);
    const float w = e / sm;

    const float* vb = value + ((size_t)(b * H_SZ + h) * S_SZ) * C_SZ + lane;
    float acc = 0.f;
    #pragma unroll
    for (int p = 0; p < P_SZ; p++) {
        const float gxp = __shfl_sync(0xffffffffu, gx, p);
        const float gyp = __shfl_sync(0xffffffffu, gy, p);
        const float wp  = __shfl_sync(0xffffffffu, w,  p);
        const int Wl = (p < 4) ? 80 : ((p < 8) ? 40 : 20);
        const int st = (p < 4) ? 0 : ((p < 8) ? 6400 : 8000);
        const float x0f = floorf(gxp), y0f = floorf(gyp);
        const float wx1 = gxp - x0f, wx0 = 1.f - wx1;
        const float wy1 = gyp - y0f, wy0 = 1.f - wy1;
        const int x0 = (int)x0f, y0 = (int)y0f, x1 = x0 + 1, y1 = y0 + 1;
        const bool xv0 = (x0 >= 0) && (x0 < Wl);
        const bool xv1 = (x1 >= 0) && (x1 < Wl);
        const bool yv0 = (y0 >= 0) && (y0 < Wl);
        const bool yv1 = (y1 >= 0) && (y1 < Wl);
        const float* lv = vb + (size_t)st * C_SZ;
        float s = 0.f;
        if (xv0 && yv0) s += wx0 * wy0 * lv[(size_t)(y0 * Wl + x0) * C_SZ];
        if (xv1 && yv0) s += wx1 * wy0 * lv[(size_t)(y0 * Wl + x1) * C_SZ];
        if (xv0 && yv1) s += wx0 * wy1 * lv[(size_t)(y1 * Wl + x0) * C_SZ];
        if (xv1 && yv1) s += wx1 * wy1 * lv[(size_t)(y1 * Wl + x1) * C_SZ];
        acc += wp * s;
    }
    mixed[(size_t)blk * 256 + h * C_SZ + lane] = acc;
}

// ---------------------------------------------------------------------------
extern "C" void kernel_launch(void* const* d_in, const int* in_sizes, int n_in,
                              void* d_out, int out_size)
{
    const float* hidden = (const float*)d_in[0];
    const float* enc    = (const float*)d_in[1];
    const float* refp   = (const float*)d_in[2];
    const float* W_off  = (const float*)d_in[3];
    const float* b_off  = (const float*)d_in[4];
    const float* W_attn = (const float*)d_in[5];
    const float* b_attn = (const float*)d_in[6];
    const float* W_val  = (const float*)d_in[7];
    const float* b_val  = (const float*)d_in[8];
    const float* W_out  = (const float*)d_in[9];
    const float* b_out  = (const float*)d_in[10];
    float* out = (float*)d_out;

    float *value, *mixed, *proj, *wproj, *bproj;
    __half* wh;
    cudaGetSymbolAddress((void**)&value, g_value);
    cudaGetSymbolAddress((void**)&mixed, g_mixed);
    cudaGetSymbolAddress((void**)&proj,  g_proj);
    cudaGetSymbolAddress((void**)&wh,    g_wh);
    cudaGetSymbolAddress((void**)&wproj, g_wproj);
    cudaGetSymbolAddress((void**)&bproj, g_bproj);

    const int M1 = B_SZ * S_SZ;   // 268800
    const int M2 = B_SZ * Q_SZ;   // 9600

    wprep_k<<<256, 256>>>(W_val, wh);
    pprep_k<<<256, 320>>>(W_off, b_off, W_attn, b_attn, wproj, bproj);

    // Stage 1: value projection (fp16 HMMA single-term)
    {
        dim3 grid(2, M1 / 128);   // (2, 2100)
        gemm_hmma_k<<<grid, 256>>>(enc, wh, b_val, value);
    }
    // Stage 2a: offset/attn projection
    {
        dim3 grid(5, M2 / 64);    // (5, 150)
        sgemm64_k<<<grid, 256>>>(hidden, wproj, bproj, proj, 320);
    }
    // Stage 2b: sampling
    sample_k<<<M2, 256>>>(proj, refp, value, mixed);

    // Stage 3: output projection
    {
        dim3 grid(4, M2 / 64);    // (4, 150)
        sgemm64_k<<<grid, 256>>>(mixed, W_out, b_out, out, 256);
    }
}

// round 8
// speedup vs baseline: 2.3443x; 1.0435x over previous
#include <cuda_runtime.h>
#include <cuda_fp16.h>
#include <cstdint>
#include <cstddef>

// RT-DETR v2 deformable attention. B=32 Q=300 d=256 H=8 C=32 S=8400 P=12
// S1: value = enc@W_val+b  (fp16 HMMA) -> (B,H,S,C) stored fp16
// S2a: proj = hidden@[W_off|W_attn|pad320]  (fp32 sgemm64)
// S2b: softmax + bilinear sampling (warp per head), fp32 accum
// S3: out = mixed@W_out+b (fp32 sgemm64)

#define B_SZ 32
#define Q_SZ 300
#define H_SZ 8
#define C_SZ 32
#define S_SZ 8400
#define P_SZ 12

__device__ __half g_value[(size_t)B_SZ * H_SZ * S_SZ * C_SZ];   // 137 MB
__device__ float  g_mixed[(size_t)B_SZ * Q_SZ * 256];
__device__ float  g_proj[(size_t)B_SZ * Q_SZ * 320];
__device__ __half g_wh[256 * 256];                               // W_val^T fp16
__device__ float  g_wproj[256 * 320];
__device__ float  g_bproj[320];

// ---------------- weight preps ----------------
__global__ void wprep_k(const float* __restrict__ W, __half* __restrict__ wh)
{
    const int n = blockIdx.x, k = threadIdx.x;
    wh[(size_t)n * 256 + k] = __float2half_rn(W[(size_t)k * 256 + n]);
}

__global__ void pprep_k(const float* __restrict__ W_off,
                        const float* __restrict__ b_off,
                        const float* __restrict__ W_attn,
                        const float* __restrict__ b_attn,
                        float* __restrict__ wp, float* __restrict__ bp)
{
    const int k = blockIdx.x, j = threadIdx.x;
    float v = 0.f, bv = 0.f;
    if (j < 192)      { v = W_off[(size_t)k * 192 + j];         bv = b_off[j]; }
    else if (j < 288) { v = W_attn[(size_t)k * 96 + (j - 192)]; bv = b_attn[j - 192]; }
    wp[(size_t)k * 320 + j] = v;
    if (k == 0) bp[j] = bv;
}

// ---------------- Stage 1: fp16 HMMA GEMM ----------------
__device__ __forceinline__ uint32_t pkhf(float x, float y) {
    __half2 t = __floats2half2_rn(x, y);
    return *reinterpret_cast<uint32_t*>(&t);
}
__device__ __forceinline__ void mma16816(float* d, const uint32_t* a,
                                         const uint32_t* b) {
    asm volatile(
        "mma.sync.aligned.m16n8k16.row.col.f32.f16.f16.f32 "
        "{%0,%1,%2,%3}, {%4,%5,%6,%7}, {%8,%9}, {%0,%1,%2,%3};"
        : "+f"(d[0]), "+f"(d[1]), "+f"(d[2]), "+f"(d[3])
        : "r"(a[0]), "r"(a[1]), "r"(a[2]), "r"(a[3]), "r"(b[0]), "r"(b[1]));
}

#define PITCH 18   // fp16 elems per smem row (16 data + 2 pad)

// C[M,256] = A[M,256] * W^T + bias, permuted fp16 store to (B,H,S,C).
// 128x128 tile, 256 threads (8 warps of 32x64), K-chunks 16, double-buffered.
__global__ __launch_bounds__(256) void gemm_hmma_k(
    const float* __restrict__ A, const __half* __restrict__ Wh,
    const float* __restrict__ bias, __half* __restrict__ C)
{
    __shared__ uint16_t sA[2][128 * PITCH];
    __shared__ uint16_t sB[2][128 * PITCH];

    const int tid  = threadIdx.x;
    const int wid  = tid >> 5;
    const int lane = tid & 31;
    const int m0 = blockIdx.y * 128;
    const int n0 = blockIdx.x * 128;

    const int m0w = (wid & 3) * 32;   // 4 M-groups of 32
    const int n0w = (wid >> 2) * 64;  // 2 N-groups of 64

    // loaders
    const int arow0 = tid >> 2,          ac0 = (tid & 3) * 4;
    const int arow1 = (tid + 256) >> 2,  ac1 = ((tid + 256) & 3) * 4;
    const int brow  = tid >> 1,          boff = (tid & 1) * 8;

    float acc[2][8][4] = {};
    float4 pa0, pa1;
    uint4  pbh;

    pa0 = *reinterpret_cast<const float4*>(&A[(size_t)(m0 + arow0) * 256 + ac0]);
    pa1 = *reinterpret_cast<const float4*>(&A[(size_t)(m0 + arow1) * 256 + ac1]);
    pbh = *reinterpret_cast<const uint4*>(&Wh[(size_t)(n0 + brow) * 256 + boff]);

#define STORE_CHUNK(BUF) do {                                              \
    {   uint16_t* p = &sA[BUF][arow0 * PITCH + ac0];                       \
        *reinterpret_cast<uint32_t*>(p)     = pkhf(pa0.x, pa0.y);          \
        *reinterpret_cast<uint32_t*>(p + 2) = pkhf(pa0.z, pa0.w);          \
    }                                                                      \
    {   uint16_t* p = &sA[BUF][arow1 * PITCH + ac1];                       \
        *reinterpret_cast<uint32_t*>(p)     = pkhf(pa1.x, pa1.y);          \
        *reinterpret_cast<uint32_t*>(p + 2) = pkhf(pa1.z, pa1.w);          \
    }                                                                      \
    {   uint16_t* p = &sB[BUF][brow * PITCH + boff];                       \
        *reinterpret_cast<uint32_t*>(p)     = pbh.x;                       \
        *reinterpret_cast<uint32_t*>(p + 2) = pbh.y;                       \
        *reinterpret_cast<uint32_t*>(p + 4) = pbh.z;                       \
        *reinterpret_cast<uint32_t*>(p + 6) = pbh.w;                       \
    }                                                                      \
} while (0)

    STORE_CHUNK(0);
    __syncthreads();

    const int lr  = lane >> 2;
    const int lc2 = (lane & 3) * 2;

    #pragma unroll 1
    for (int c = 0; c < 16; ++c) {
        const int buf = c & 1;
        if (c < 15) {
            const int k0 = (c + 1) * 16;
            pa0 = *reinterpret_cast<const float4*>(&A[(size_t)(m0 + arow0) * 256 + k0 + ac0]);
            pa1 = *reinterpret_cast<const float4*>(&A[(size_t)(m0 + arow1) * 256 + k0 + ac1]);
            pbh = *reinterpret_cast<const uint4*>(&Wh[(size_t)(n0 + brow) * 256 + k0 + boff]);
        }

        uint32_t ah[2][4], bh[8][2];
        #pragma unroll
        for (int mt = 0; mt < 2; mt++) {
            const int r = m0w + mt * 16 + lr;
            ah[mt][0] = *reinterpret_cast<const uint32_t*>(&sA[buf][r * PITCH + lc2]);
            ah[mt][1] = *reinterpret_cast<const uint32_t*>(&sA[buf][(r + 8) * PITCH + lc2]);
            ah[mt][2] = *reinterpret_cast<const uint32_t*>(&sA[buf][r * PITCH + lc2 + 8]);
            ah[mt][3] = *reinterpret_cast<const uint32_t*>(&sA[buf][(r + 8) * PITCH + lc2 + 8]);
        }
        #pragma unroll
        for (int nt = 0; nt < 8; nt++) {
            const int r = n0w + nt * 8 + lr;
            bh[nt][0] = *reinterpret_cast<const uint32_t*>(&sB[buf][r * PITCH + lc2]);
            bh[nt][1] = *reinterpret_cast<const uint32_t*>(&sB[buf][r * PITCH + lc2 + 8]);
        }

        #pragma unroll
        for (int mt = 0; mt < 2; mt++)
            #pragma unroll
            for (int nt = 0; nt < 8; nt++)
                mma16816(acc[mt][nt], ah[mt], bh[nt]);

        if (c < 15) {
            STORE_CHUNK(buf ^ 1);
            __syncthreads();
        }
    }
#undef STORE_CHUNK

    // epilogue: permuted fp16 store (B,H,S,C) with bias
    #pragma unroll
    for (int mt = 0; mt < 2; mt++) {
        const int mA = m0 + m0w + mt * 16 + lr;
        const int mB = mA + 8;
        const int bbA = mA / S_SZ, ssA = mA % S_SZ;
        const int bbB = mB / S_SZ, ssB = mB % S_SZ;
        #pragma unroll
        for (int nt = 0; nt < 8; nt++) {
            const int n = n0 + n0w + nt * 8 + lc2;
            const int h = n >> 5, cc = n & 31;
            const float bi0 = bias[n], bi1 = bias[n + 1];
            const __half2 v0 = __floats2half2_rn(acc[mt][nt][0] + bi0,
                                                 acc[mt][nt][1] + bi1);
            const __half2 v1 = __floats2half2_rn(acc[mt][nt][2] + bi0,
                                                 acc[mt][nt][3] + bi1);
            *reinterpret_cast<__half2*>(
                &C[(((size_t)(bbA * H_SZ + h)) * S_SZ + ssA) * C_SZ + cc]) = v0;
            *reinterpret_cast<__half2*>(
                &C[(((size_t)(bbB * H_SZ + h)) * S_SZ + ssB) * C_SZ + cc]) = v1;
        }
    }
}

// ---------------- fp32 SGEMM 64x64 ----------------
__global__ __launch_bounds__(256) void sgemm64_k(
    const float* __restrict__ A, const float* __restrict__ Bm,
    const float* __restrict__ bias, float* __restrict__ C, int N)
{
    __shared__ float As[16][68];
    __shared__ float Bs[16][68];

    const int tid = threadIdx.x;
    const int m0 = blockIdx.y * 64, n0 = blockIdx.x * 64;
    const int ty = tid >> 4, tx = tid & 15;
    const int arow = tid >> 2, akq = tid & 3;
    const int bkk = tid >> 4, bnq = tid & 15;

    float acc[4][4] = {};

    for (int k0 = 0; k0 < 256; k0 += 16) {
        float4 av = *reinterpret_cast<const float4*>(
            &A[(size_t)(m0 + arow) * 256 + k0 + akq * 4]);
        As[akq * 4 + 0][arow] = av.x;
        As[akq * 4 + 1][arow] = av.y;
        As[akq * 4 + 2][arow] = av.z;
        As[akq * 4 + 3][arow] = av.w;
        *reinterpret_cast<float4*>(&Bs[bkk][bnq * 4]) =
            *reinterpret_cast<const float4*>(&Bm[(size_t)(k0 + bkk) * N + n0 + bnq * 4]);
        __syncthreads();
        #pragma unroll
        for (int kk = 0; kk < 16; kk++) {
            float4 ra = *reinterpret_cast<const float4*>(&As[kk][ty * 4]);
            float4 rb = *reinterpret_cast<const float4*>(&Bs[kk][tx * 4]);
            float a_[4] = {ra.x, ra.y, ra.z, ra.w};
            float b_[4] = {rb.x, rb.y, rb.z, rb.w};
            #pragma unroll
            for (int i = 0; i < 4; i++)
                #pragma unroll
                for (int j = 0; j < 4; j++)
                    acc[i][j] += a_[i] * b_[j];
        }
        __syncthreads();
    }

    #pragma unroll
    for (int i = 0; i < 4; i++) {
        const int m = m0 + ty * 4 + i;
        const int n = n0 + tx * 4;
        float4 v;
        v.x = acc[i][0] + bias[n + 0];
        v.y = acc[i][1] + bias[n + 1];
        v.z = acc[i][2] + bias[n + 2];
        v.w = acc[i][3] + bias[n + 3];
        *reinterpret_cast<float4*>(&C[(size_t)m * N + n]) = v;
    }
}

// ---------------- Stage 2b: sampling (fp16 value) ----------------
__global__ __launch_bounds__(256) void sample_k(
    const float* __restrict__ proj, const float* __restrict__ refp,
    const __half* __restrict__ value, float* __restrict__ mixed)
{
    const int blk = blockIdx.x;        // b*Q + q
    const int b = blk / Q_SZ;
    const int h = threadIdx.x >> 5;
    const int lane = threadIdx.x & 31;

    const float rx = __ldg(&refp[blk * 4 + 0]);
    const float ry = __ldg(&refp[blk * 4 + 1]);
    const float rw = __ldg(&refp[blk * 4 + 2]);
    const float rh = __ldg(&refp[blk * 4 + 3]);

    float gx = 0.f, gy = 0.f, logit = -1e30f;
    if (lane < P_SZ) {
        const float ox = __ldg(&proj[(size_t)blk * 320 + (h * P_SZ + lane) * 2]);
        const float oy = __ldg(&proj[(size_t)blk * 320 + (h * P_SZ + lane) * 2 + 1]);
        logit = __ldg(&proj[(size_t)blk * 320 + 192 + h * P_SZ + lane]);
        const float Wf = (lane < 4) ? 80.f : ((lane < 8) ? 40.f : 20.f);
        gx = (rx + ox * rw * 0.125f) * Wf - 0.5f;
        gy = (ry + oy * rh * 0.125f) * Wf - 0.5f;
    }
    float mx = logit;
    #pragma unroll
    for (int o = 16; o; o >>= 1) mx = fmaxf(mx, __shfl_xor_sync(0xffffffffu, mx, o));
    const float e = (lane < P_SZ) ? __expf(logit - mx) : 0.f;
    float sm = e;
    #pragma unroll
    for (int o = 16; o; o >>= 1) sm += __shfl_xor_sync(0xffffffffu, sm, o);
    const float w = e / sm;

    const __half* vb = value + ((size_t)(b * H_SZ + h) * S_SZ) * C_SZ + lane;
    float acc = 0.f;
    #pragma unroll
    for (int p = 0; p < P_SZ; p++) {
        const float gxp = __shfl_sync(0xffffffffu, gx, p);
        const float gyp = __shfl_sync(0xffffffffu, gy, p);
        const float wp  = __shfl_sync(0xffffffffu, w,  p);
        const int Wl = (p < 4) ? 80 : ((p < 8) ? 40 : 20);
        const int st = (p < 4) ? 0 : ((p < 8) ? 6400 : 8000);
        const float x0f = floorf(gxp), y0f = floorf(gyp);
        const float wx1 = gxp - x0f, wx0 = 1.f - wx1;
        const float wy1 = gyp - y0f, wy0 = 1.f - wy1;
        const int x0 = (int)x0f, y0 = (int)y0f, x1 = x0 + 1, y1 = y0 + 1;
        const bool xv0 = (x0 >= 0) && (x0 < Wl);
        const bool xv1 = (x1 >= 0) && (x1 < Wl);
        const bool yv0 = (y0 >= 0) && (y0 < Wl);
        const bool yv1 = (y1 >= 0) && (y1 < Wl);
        const __half* lv = vb + (size_t)st * C_SZ;
        float s = 0.f;
        if (xv0 && yv0) s += wx0 * wy0 * __half2float(lv[(size_t)(y0 * Wl + x0) * C_SZ]);
        if (xv1 && yv0) s += wx1 * wy0 * __half2float(lv[(size_t)(y0 * Wl + x1) * C_SZ]);
        if (xv0 && yv1) s += wx0 * wy1 * __half2float(lv[(size_t)(y1 * Wl + x0) * C_SZ]);
        if (xv1 && yv1) s += wx1 * wy1 * __half2float(lv[(size_t)(y1 * Wl + x1) * C_SZ]);
        acc += wp * s;
    }
    mixed[(size_t)blk * 256 + h * C_SZ + lane] = acc;
}

// ---------------------------------------------------------------------------
extern "C" void kernel_launch(void* const* d_in, const int* in_sizes, int n_in,
                              void* d_out, int out_size)
{
    const float* hidden = (const float*)d_in[0];
    const float* enc    = (const float*)d_in[1];
    const float* refp   = (const float*)d_in[2];
    const float* W_off  = (const float*)d_in[3];
    const float* b_off  = (const float*)d_in[4];
    const float* W_attn = (const float*)d_in[5];
    const float* b_attn = (const float*)d_in[6];
    const float* W_val  = (const float*)d_in[7];
    const float* b_val  = (const float*)d_in[8];
    const float* W_out  = (const float*)d_in[9];
    const float* b_out  = (const float*)d_in[10];
    float* out = (float*)d_out;

    float *mixed, *proj, *wproj, *bproj;
    __half *value, *wh;
    cudaGetSymbolAddress((void**)&value, g_value);
    cudaGetSymbolAddress((void**)&mixed, g_mixed);
    cudaGetSymbolAddress((void**)&proj,  g_proj);
    cudaGetSymbolAddress((void**)&wh,    g_wh);
    cudaGetSymbolAddress((void**)&wproj, g_wproj);
    cudaGetSymbolAddress((void**)&bproj, g_bproj);

    const int M1 = B_SZ * S_SZ;   // 268800
    const int M2 = B_SZ * Q_SZ;   // 9600

    wprep_k<<<256, 256>>>(W_val, wh);
    pprep_k<<<256, 320>>>(W_off, b_off, W_attn, b_attn, wproj, bproj);

    // Stage 1: value projection (fp16 HMMA), fp16 permuted store
    {
        dim3 grid(2, M1 / 128);   // (2, 2100)
        gemm_hmma_k<<<grid, 256>>>(enc, wh, b_val, value);
    }
    // Stage 2a: offset/attn projection
    {
        dim3 grid(5, M2 / 64);    // (5, 150)
        sgemm64_k<<<grid, 256>>>(hidden, wproj, bproj, proj, 320);
    }
    // Stage 2b: sampling
    sample_k<<<M2, 256>>>(proj, refp, value, mixed);

    // Stage 3: output projection
    {
        dim3 grid(4, M2 / 64);    // (4, 150)
        sgemm64_k<<<grid, 256>>>(mixed, W_out, b_out, out, 256);
    }
}

// round 10
// speedup vs baseline: 2.7311x; 1.1650x over previous
#include <cuda_runtime.h>
#include <cuda_fp16.h>
#include <cstdint>
#include <cstddef>

// RT-DETR v2 deformable attention. B=32 Q=300 d=256 H=8 C=32 S=8400 P=12
// S1: value = enc@W_val+b  (fp16 HMMA) -> (B,H,S,C) fp16
// S2a: proj = hidden@[W_off|W_attn|pad384] (fp16 HMMA, fp32 out)
// S2b: softmax + bilinear sampling (warp/head, dual-point half2 lanes)
// S3: out = mixed@W_out+b (fp16 HMMA, fp32 out)

#define B_SZ 32
#define Q_SZ 300
#define H_SZ 8
#define C_SZ 32
#define S_SZ 8400
#define P_SZ 12
#define PROJ_N 384

__device__ __half g_value[(size_t)B_SZ * H_SZ * S_SZ * C_SZ];   // 137 MB
__device__ float  g_mixed[(size_t)B_SZ * Q_SZ * 256];
__device__ float  g_proj[(size_t)B_SZ * Q_SZ * PROJ_N];
__device__ __half g_wh[256 * 256];                               // W_val^T
__device__ __half g_woh[256 * 256];                              // W_out^T
__device__ __half g_wph[PROJ_N * 256];                           // [Woff|Wattn]^T
__device__ float  g_bproj[PROJ_N];

// ---------------- weight preps ----------------
__global__ void wprep_k(const float* __restrict__ W, __half* __restrict__ wh)
{
    const int n = blockIdx.x, k = threadIdx.x;
    wh[(size_t)n * 256 + k] = __float2half_rn(W[(size_t)k * 256 + n]);
}

__global__ void pprep_k(const float* __restrict__ W_off,
                        const float* __restrict__ b_off,
                        const float* __restrict__ W_attn,
                        const float* __restrict__ b_attn,
                        __half* __restrict__ wph, float* __restrict__ bp)
{
    const int n = blockIdx.x, k = threadIdx.x;   // n<384, k<256
    float v = 0.f, bv = 0.f;
    if (n < 192)      { v = W_off[(size_t)k * 192 + n];         bv = b_off[n]; }
    else if (n < 288) { v = W_attn[(size_t)k * 96 + (n - 192)]; bv = b_attn[n - 192]; }
    wph[(size_t)n * 256 + k] = __float2half_rn(v);
    if (k == 0) bp[n] = bv;
}

// ---------------- HMMA helpers ----------------
__device__ __forceinline__ uint32_t pkhf(float x, float y) {
    __half2 t = __floats2half2_rn(x, y);
    return *reinterpret_cast<uint32_t*>(&t);
}
__device__ __forceinline__ void mma16816(float* d, const uint32_t* a,
                                         const uint32_t* b) {
    asm volatile(
        "mma.sync.aligned.m16n8k16.row.col.f32.f16.f16.f32 "
        "{%0,%1,%2,%3}, {%4,%5,%6,%7}, {%8,%9}, {%0,%1,%2,%3};"
        : "+f"(d[0]), "+f"(d[1]), "+f"(d[2]), "+f"(d[3])
        : "r"(a[0]), "r"(a[1]), "r"(a[2]), "r"(a[3]), "r"(b[0]), "r"(b[1]));
}

#define PITCH 18

// C[M,256] = A[M,256]*Wh^T + bias.
// PERM=true: fp16 store permuted to (B,H,S,C) (Cd used). PERM=false: fp32
// row-major stride Ns (Cf used). 128x128 tile, 8 warps, K-chunk 16, dbl-buf.
template <bool PERM>
__global__ __launch_bounds__(256) void gemm_hmma_k(
    const float* __restrict__ A, const __half* __restrict__ Wh,
    const float* __restrict__ bias, __half* __restrict__ Cd,
    float* __restrict__ Cf, int Ns)
{
    __shared__ uint16_t sA[2][128 * PITCH];
    __shared__ uint16_t sB[2][128 * PITCH];

    const int tid  = threadIdx.x;
    const int wid  = tid >> 5;
    const int lane = tid & 31;
    const int m0 = blockIdx.y * 128;
    const int n0 = blockIdx.x * 128;
    const int m0w = (wid & 3) * 32;
    const int n0w = (wid >> 2) * 64;

    const int arow0 = tid >> 2,          ac0 = (tid & 3) * 4;
    const int arow1 = (tid + 256) >> 2,  ac1 = ((tid + 256) & 3) * 4;
    const int brow  = tid >> 1,          boff = (tid & 1) * 8;

    float acc[2][8][4] = {};
    float4 pa0, pa1;
    uint4  pbh;

    pa0 = *reinterpret_cast<const float4*>(&A[(size_t)(m0 + arow0) * 256 + ac0]);
    pa1 = *reinterpret_cast<const float4*>(&A[(size_t)(m0 + arow1) * 256 + ac1]);
    pbh = *reinterpret_cast<const uint4*>(&Wh[(size_t)(n0 + brow) * 256 + boff]);

#define STORE_CHUNK(BUF) do {                                              \
    {   uint16_t* p = &sA[BUF][arow0 * PITCH + ac0];                       \
        *reinterpret_cast<uint32_t*>(p)     = pkhf(pa0.x, pa0.y);          \
        *reinterpret_cast<uint32_t*>(p + 2) = pkhf(pa0.z, pa0.w);          \
    }                                                                      \
    {   uint16_t* p = &sA[BUF][arow1 * PITCH + ac1];                       \
        *reinterpret_cast<uint32_t*>(p)     = pkhf(pa1.x, pa1.y);          \
        *reinterpret_cast<uint32_t*>(p + 2) = pkhf(pa1.z, pa1.w);          \
    }                                                                      \
    {   uint16_t* p = &sB[BUF][brow * PITCH + boff];                       \
        *reinterpret_cast<uint32_t*>(p)     = pbh.x;                       \
        *reinterpret_cast<uint32_t*>(p + 2) = pbh.y;                       \
        *reinterpret_cast<uint32_t*>(p + 4) = pbh.z;                       \
        *reinterpret_cast<uint32_t*>(p + 6) = pbh.w;                       \
    }                                                                      \
} while (0)

    STORE_CHUNK(0);
    __syncthreads();

    const int lr  = lane >> 2;
    const int lc2 = (lane & 3) * 2;

    #pragma unroll 1
    for (int c = 0; c < 16; ++c) {
        const int buf = c & 1;
        if (c < 15) {
            const int k0 = (c + 1) * 16;
            pa0 = *reinterpret_cast<const float4*>(&A[(size_t)(m0 + arow0) * 256 + k0 + ac0]);
            pa1 = *reinterpret_cast<const float4*>(&A[(size_t)(m0 + arow1) * 256 + k0 + ac1]);
            pbh = *reinterpret_cast<const uint4*>(&Wh[(size_t)(n0 + brow) * 256 + k0 + boff]);
        }

        uint32_t ah[2][4], bh[8][2];
        #pragma unroll
        for (int mt = 0; mt < 2; mt++) {
            const int r = m0w + mt * 16 + lr;
            ah[mt][0] = *reinterpret_cast<const uint32_t*>(&sA[buf][r * PITCH + lc2]);
            ah[mt][1] = *reinterpret_cast<const uint32_t*>(&sA[buf][(r + 8) * PITCH + lc2]);
            ah[mt][2] = *reinterpret_cast<const uint32_t*>(&sA[buf][r * PITCH + lc2 + 8]);
            ah[mt][3] = *reinterpret_cast<const uint32_t*>(&sA[buf][(r + 8) * PITCH + lc2 + 8]);
        }
        #pragma unroll
        for (int nt = 0; nt < 8; nt++) {
            const int r = n0w + nt * 8 + lr;
            bh[nt][0] = *reinterpret_cast<const uint32_t*>(&sB[buf][r * PITCH + lc2]);
            bh[nt][1] = *reinterpret_cast<const uint32_t*>(&sB[buf][r * PITCH + lc2 + 8]);
        }

        #pragma unroll
        for (int mt = 0; mt < 2; mt++)
            #pragma unroll
            for (int nt = 0; nt < 8; nt++)
                mma16816(acc[mt][nt], ah[mt], bh[nt]);

        if (c < 15) {
            STORE_CHUNK(buf ^ 1);
            __syncthreads();
        }
    }
#undef STORE_CHUNK

    #pragma unroll
    for (int mt = 0; mt < 2; mt++) {
        const int mA = m0 + m0w + mt * 16 + lr;
        const int mB = mA + 8;
        int bbA = 0, ssA = 0, bbB = 0, ssB = 0;
        if (PERM) {
            bbA = mA / S_SZ; ssA = mA % S_SZ;
            bbB = mB / S_SZ; ssB = mB % S_SZ;
        }
        #pragma unroll
        for (int nt = 0; nt < 8; nt++) {
            const int n = n0 + n0w + nt * 8 + lc2;
            const float bi0 = bias[n], bi1 = bias[n + 1];
            if (PERM) {
                const int h = n >> 5, cc = n & 31;
                const __half2 v0 = __floats2half2_rn(acc[mt][nt][0] + bi0,
                                                     acc[mt][nt][1] + bi1);
                const __half2 v1 = __floats2half2_rn(acc[mt][nt][2] + bi0,
                                                     acc[mt][nt][3] + bi1);
                *reinterpret_cast<__half2*>(
                    &Cd[(((size_t)(bbA * H_SZ + h)) * S_SZ + ssA) * C_SZ + cc]) = v0;
                *reinterpret_cast<__half2*>(
                    &Cd[(((size_t)(bbB * H_SZ + h)) * S_SZ + ssB) * C_SZ + cc]) = v1;
            } else {
                float2 v0, v1;
                v0.x = acc[mt][nt][0] + bi0;
                v0.y = acc[mt][nt][1] + bi1;
                v1.x = acc[mt][nt][2] + bi0;
                v1.y = acc[mt][nt][3] + bi1;
                *reinterpret_cast<float2*>(&Cf[(size_t)mA * Ns + n]) = v0;
                *reinterpret_cast<float2*>(&Cf[(size_t)mB * Ns + n]) = v1;
            }
        }
    }
}

// ---------------- Stage 2b: sampling (dual-point half2) ----------------
__global__ __launch_bounds__(256) void sample_k(
    const float* __restrict__ proj, const float* __restrict__ refp,
    const __half* __restrict__ value, float* __restrict__ mixed)
{
    const int blk = blockIdx.x;        // b*Q + q
    const int b = blk / Q_SZ;
    const int h = threadIdx.x >> 5;
    const int lane = threadIdx.x & 31;

    const float rx = __ldg(&refp[blk * 4 + 0]);
    const float ry = __ldg(&refp[blk * 4 + 1]);
    const float rw = __ldg(&refp[blk * 4 + 2]);
    const float rh = __ldg(&refp[blk * 4 + 3]);

    float gx = 0.f, gy = 0.f, logit = -1e30f;
    if (lane < P_SZ) {
        const float ox = __ldg(&proj[(size_t)blk * PROJ_N + (h * P_SZ + lane) * 2]);
        const float oy = __ldg(&proj[(size_t)blk * PROJ_N + (h * P_SZ + lane) * 2 + 1]);
        logit = __ldg(&proj[(size_t)blk * PROJ_N + 192 + h * P_SZ + lane]);
        const float Wf = (lane < 4) ? 80.f : ((lane < 8) ? 40.f : 20.f);
        gx = (rx + ox * rw * 0.125f) * Wf - 0.5f;
        gy = (ry + oy * rh * 0.125f) * Wf - 0.5f;
    }
    float mx = logit;
    #pragma unroll
    for (int o = 16; o; o >>= 1) mx = fmaxf(mx, __shfl_xor_sync(0xffffffffu, mx, o));
    const float e = (lane < P_SZ) ? __expf(logit - mx) : 0.f;
    float sm = e;
    #pragma unroll
    for (int o = 16; o; o >>= 1) sm += __shfl_xor_sync(0xffffffffu, sm, o);
    const float w = e / sm;

    // lanes 0-15: even p, lanes 16-31: odd p; lane owns channel pair c2.
    const int c2 = (lane & 15) * 2;
    const int psel = lane >> 4;
    const __half* vbase = value + ((size_t)(b * H_SZ + h) * S_SZ) * C_SZ + c2;

    float accx = 0.f, accy = 0.f;
    #pragma unroll
    for (int pp = 0; pp < 6; pp++) {
        const int p = pp * 2 + psel;
        const float gxp = __shfl_sync(0xffffffffu, gx, p);
        const float gyp = __shfl_sync(0xffffffffu, gy, p);
        const float wp  = __shfl_sync(0xffffffffu, w,  p);
        const int Wl = (pp < 2) ? 80 : ((pp < 4) ? 40 : 20);
        const int st = (pp < 2) ? 0 : ((pp < 4) ? 6400 : 8000);
        const float x0f = floorf(gxp), y0f = floorf(gyp);
        const float wx1 = gxp - x0f, wx0 = 1.f - wx1;
        const float wy1 = gyp - y0f, wy0 = 1.f - wy1;
        const int x0 = (int)x0f, y0 = (int)y0f, x1 = x0 + 1, y1 = y0 + 1;
        const bool xv0 = (x0 >= 0) && (x0 < Wl);
        const bool xv1 = (x1 >= 0) && (x1 < Wl);
        const bool yv0 = (y0 >= 0) && (y0 < Wl);
        const bool yv1 = (y1 >= 0) && (y1 < Wl);
        const __half* lv = vbase + (size_t)st * C_SZ;

        float tx = 0.f, ty = 0.f;
        if (xv0 && yv0) {
            const float2 v = __half22float2(
                *reinterpret_cast<const __half2*>(lv + (size_t)(y0 * Wl + x0) * C_SZ));
            const float tw = wx0 * wy0;
            tx += tw * v.x; ty += tw * v.y;
        }
        if (xv1 && yv0) {
            const float2 v = __half22float2(
                *reinterpret_cast<const __half2*>(lv + (size_t)(y0 * Wl + x1) * C_SZ));
            const float tw = wx1 * wy0;
            tx += tw * v.x; ty += tw * v.y;
        }
        if (xv0 && yv1) {
            const float2 v = __half22float2(
                *reinterpret_cast<const __half2*>(lv + (size_t)(y1 * Wl + x0) * C_SZ));
            const float tw = wx0 * wy1;
            tx += tw * v.x; ty += tw * v.y;
        }
        if (xv1 && yv1) {
            const float2 v = __half22float2(
                *reinterpret_cast<const __half2*>(lv + (size_t)(y1 * Wl + x1) * C_SZ));
            const float tw = wx1 * wy1;
            tx += tw * v.x; ty += tw * v.y;
        }
        accx += wp * tx;
        accy += wp * ty;
    }
    accx += __shfl_xor_sync(0xffffffffu, accx, 16);
    accy += __shfl_xor_sync(0xffffffffu, accy, 16);
    if (lane < 16) {
        float2 o; o.x = accx; o.y = accy;
        *reinterpret_cast<float2*>(&mixed[(size_t)blk * 256 + h * C_SZ + c2]) = o;
    }
}

// ---------------------------------------------------------------------------
extern "C" void kernel_launch(void* const* d_in, const int* in_sizes, int n_in,
                              void* d_out, int out_size)
{
    const float* hidden = (const float*)d_in[0];
    const float* enc    = (const float*)d_in[1];
    const float* refp   = (const float*)d_in[2];
    const float* W_off  = (const float*)d_in[3];
    const float* b_off  = (const float*)d_in[4];
    const float* W_attn = (const float*)d_in[5];
    const float* b_attn = (const float*)d_in[6];
    const float* W_val  = (const float*)d_in[7];
    const float* b_val  = (const float*)d_in[8];
    const float* W_out  = (const float*)d_in[9];
    const float* b_out  = (const float*)d_in[10];
    float* out = (float*)d_out;

    float *mixed, *proj, *bproj;
    __half *value, *wh, *woh, *wph;
    cudaGetSymbolAddress((void**)&value, g_value);
    cudaGetSymbolAddress((void**)&mixed, g_mixed);
    cudaGetSymbolAddress((void**)&proj,  g_proj);
    cudaGetSymbolAddress((void**)&wh,    g_wh);
    cudaGetSymbolAddress((void**)&woh,   g_woh);
    cudaGetSymbolAddress((void**)&wph,   g_wph);
    cudaGetSymbolAddress((void**)&bproj, g_bproj);

    const int M1 = B_SZ * S_SZ;   // 268800
    const int M2 = B_SZ * Q_SZ;   // 9600

    wprep_k<<<256, 256>>>(W_val, wh);
    wprep_k<<<256, 256>>>(W_out, woh);
    pprep_k<<<PROJ_N, 256>>>(W_off, b_off, W_attn, b_attn, wph, bproj);

    // Stage 1: value projection (fp16 HMMA), fp16 permuted store
    {
        dim3 grid(2, M1 / 128);   // (2, 2100)
        gemm_hmma_k<true><<<grid, 256>>>(enc, wh, b_val, value, nullptr, 0);
    }
    // Stage 2a: offset/attn projection (fp16 HMMA, fp32 out, N=384)
    {
        dim3 grid(PROJ_N / 128, M2 / 128);   // (3, 75)
        gemm_hmma_k<false><<<grid, 256>>>(hidden, wph, bproj, nullptr, proj, PROJ_N);
    }
    // Stage 2b: sampling
    sample_k<<<M2, 256>>>(proj, refp, value, mixed);

    // Stage 3: output projection (fp16 HMMA, fp32 out, N=256)
    {
        dim3 grid(2, M2 / 128);   // (2, 75)
        gemm_hmma_k<false><<<grid, 256>>>(mixed, woh, b_out, nullptr, out, 256);
    }
}

// round 11
// speedup vs baseline: 3.0885x; 1.1309x over previous
#include <cuda_runtime.h>
#include <cuda_fp16.h>
#include <cstdint>
#include <cstddef>

// RT-DETR v2 deformable attention. B=32 Q=300 d=256 H=8 C=32 S=8400 P=12
// S1: value = enc@W_val+b  (fp16 HMMA) -> (B,H,S,C) fp16
// S2a: proj = hidden@[W_off|W_attn|pad384] (fp16 HMMA, fp32 out)
// S2b: softmax + bilinear sampling (warp/head, dual-point half2 lanes)
// S3: out = mixed@W_out+b (fp16 HMMA, fp32 out)
// R11: PITCH 18 -> 24 (conflict-free fragment LDS: 12 banks/row stride)

#define B_SZ 32
#define Q_SZ 300
#define H_SZ 8
#define C_SZ 32
#define S_SZ 8400
#define P_SZ 12
#define PROJ_N 384

__device__ __half g_value[(size_t)B_SZ * H_SZ * S_SZ * C_SZ];   // 137 MB
__device__ float  g_mixed[(size_t)B_SZ * Q_SZ * 256];
__device__ float  g_proj[(size_t)B_SZ * Q_SZ * PROJ_N];
__device__ __half g_wh[256 * 256];                               // W_val^T
__device__ __half g_woh[256 * 256];                              // W_out^T
__device__ __half g_wph[PROJ_N * 256];                           // [Woff|Wattn]^T
__device__ float  g_bproj[PROJ_N];

// ---------------- weight preps ----------------
__global__ void wprep_k(const float* __restrict__ W, __half* __restrict__ wh)
{
    const int n = blockIdx.x, k = threadIdx.x;
    wh[(size_t)n * 256 + k] = __float2half_rn(W[(size_t)k * 256 + n]);
}

__global__ void pprep_k(const float* __restrict__ W_off,
                        const float* __restrict__ b_off,
                        const float* __restrict__ W_attn,
                        const float* __restrict__ b_attn,
                        __half* __restrict__ wph, float* __restrict__ bp)
{
    const int n = blockIdx.x, k = threadIdx.x;   // n<384, k<256
    float v = 0.f, bv = 0.f;
    if (n < 192)      { v = W_off[(size_t)k * 192 + n];         bv = b_off[n]; }
    else if (n < 288) { v = W_attn[(size_t)k * 96 + (n - 192)]; bv = b_attn[n - 192]; }
    wph[(size_t)n * 256 + k] = __float2half_rn(v);
    if (k == 0) bp[n] = bv;
}

// ---------------- HMMA helpers ----------------
__device__ __forceinline__ uint32_t pkhf(float x, float y) {
    __half2 t = __floats2half2_rn(x, y);
    return *reinterpret_cast<uint32_t*>(&t);
}
__device__ __forceinline__ void mma16816(float* d, const uint32_t* a,
                                         const uint32_t* b) {
    asm volatile(
        "mma.sync.aligned.m16n8k16.row.col.f32.f16.f16.f32 "
        "{%0,%1,%2,%3}, {%4,%5,%6,%7}, {%8,%9}, {%0,%1,%2,%3};"
        : "+f"(d[0]), "+f"(d[1]), "+f"(d[2]), "+f"(d[3])
        : "r"(a[0]), "r"(a[1]), "r"(a[2]), "r"(a[3]), "r"(b[0]), "r"(b[1]));
}

// 24 halfs = 48 B row stride = 12 banks. Fragment LDS: bank = 12*r + c,
// r in 0..7 -> bases {0,12,24,4,16,28,8,20}, gaps >= 4 > c-range 0..3
// -> conflict-free for all fragment offsets (+8-half offset shifts same set).
#define PITCH 24

// C[M,256] = A[M,256]*Wh^T + bias.
// PERM=true: fp16 store permuted to (B,H,S,C) (Cd). PERM=false: fp32
// row-major stride Ns (Cf). 128x128 tile, 8 warps, K-chunk 16, dbl-buf.
template <bool PERM>
__global__ __launch_bounds__(256) void gemm_hmma_k(
    const float* __restrict__ A, const __half* __restrict__ Wh,
    const float* __restrict__ bias, __half* __restrict__ Cd,
    float* __restrict__ Cf, int Ns)
{
    __shared__ uint16_t sA[2][128 * PITCH];
    __shared__ uint16_t sB[2][128 * PITCH];

    const int tid  = threadIdx.x;
    const int wid  = tid >> 5;
    const int lane = tid & 31;
    const int m0 = blockIdx.y * 128;
    const int n0 = blockIdx.x * 128;
    const int m0w = (wid & 3) * 32;
    const int n0w = (wid >> 2) * 64;

    const int arow0 = tid >> 2,          ac0 = (tid & 3) * 4;
    const int arow1 = (tid + 256) >> 2,  ac1 = ((tid + 256) & 3) * 4;
    const int brow  = tid >> 1,          boff = (tid & 1) * 8;

    float acc[2][8][4] = {};
    float4 pa0, pa1;
    uint4  pbh;

    pa0 = *reinterpret_cast<const float4*>(&A[(size_t)(m0 + arow0) * 256 + ac0]);
    pa1 = *reinterpret_cast<const float4*>(&A[(size_t)(m0 + arow1) * 256 + ac1]);
    pbh = *reinterpret_cast<const uint4*>(&Wh[(size_t)(n0 + brow) * 256 + boff]);

#define STORE_CHUNK(BUF) do {                                              \
    {   uint16_t* p = &sA[BUF][arow0 * PITCH + ac0];                       \
        *reinterpret_cast<uint32_t*>(p)     = pkhf(pa0.x, pa0.y);          \
        *reinterpret_cast<uint32_t*>(p + 2) = pkhf(pa0.z, pa0.w);          \
    }                                                                      \
    {   uint16_t* p = &sA[BUF][arow1 * PITCH + ac1];                       \
        *reinterpret_cast<uint32_t*>(p)     = pkhf(pa1.x, pa1.y);          \
        *reinterpret_cast<uint32_t*>(p + 2) = pkhf(pa1.z, pa1.w);          \
    }                                                                      \
    {   uint16_t* p = &sB[BUF][brow * PITCH + boff];                       \
        *reinterpret_cast<uint32_t*>(p)     = pbh.x;                       \
        *reinterpret_cast<uint32_t*>(p + 2) = pbh.y;                       \
        *reinterpret_cast<uint32_t*>(p + 4) = pbh.z;                       \
        *reinterpret_cast<uint32_t*>(p + 6) = pbh.w;                       \
    }                                                                      \
} while (0)

    STORE_CHUNK(0);
    __syncthreads();

    const int lr  = lane >> 2;
    const int lc2 = (lane & 3) * 2;

    #pragma unroll 1
    for (int c = 0; c < 16; ++c) {
        const int buf = c & 1;
        if (c < 15) {
            const int k0 = (c + 1) * 16;
            pa0 = *reinterpret_cast<const float4*>(&A[(size_t)(m0 + arow0) * 256 + k0 + ac0]);
            pa1 = *reinterpret_cast<const float4*>(&A[(size_t)(m0 + arow1) * 256 + k0 + ac1]);
            pbh = *reinterpret_cast<const uint4*>(&Wh[(size_t)(n0 + brow) * 256 + k0 + boff]);
        }

        uint32_t ah[2][4], bh[8][2];
        #pragma unroll
        for (int mt = 0; mt < 2; mt++) {
            const int r = m0w + mt * 16 + lr;
            ah[mt][0] = *reinterpret_cast<const uint32_t*>(&sA[buf][r * PITCH + lc2]);
            ah[mt][1] = *reinterpret_cast<const uint32_t*>(&sA[buf][(r + 8) * PITCH + lc2]);
            ah[mt][2] = *reinterpret_cast<const uint32_t*>(&sA[buf][r * PITCH + lc2 + 8]);
            ah[mt][3] = *reinterpret_cast<const uint32_t*>(&sA[buf][(r + 8) * PITCH + lc2 + 8]);
        }
        #pragma unroll
        for (int nt = 0; nt < 8; nt++) {
            const int r = n0w + nt * 8 + lr;
            bh[nt][0] = *reinterpret_cast<const uint32_t*>(&sB[buf][r * PITCH + lc2]);
            bh[nt][1] = *reinterpret_cast<const uint32_t*>(&sB[buf][r * PITCH + lc2 + 8]);
        }

        #pragma unroll
        for (int mt = 0; mt < 2; mt++)
            #pragma unroll
            for (int nt = 0; nt < 8; nt++)
                mma16816(acc[mt][nt], ah[mt], bh[nt]);

        if (c < 15) {
            STORE_CHUNK(buf ^ 1);
            __syncthreads();
        }
    }
#undef STORE_CHUNK

    #pragma unroll
    for (int mt = 0; mt < 2; mt++) {
        const int mA = m0 + m0w + mt * 16 + lr;
        const int mB = mA + 8;
        int bbA = 0, ssA = 0, bbB = 0, ssB = 0;
        if (PERM) {
            bbA = mA / S_SZ; ssA = mA % S_SZ;
            bbB = mB / S_SZ; ssB = mB % S_SZ;
        }
        #pragma unroll
        for (int nt = 0; nt < 8; nt++) {
            const int n = n0 + n0w + nt * 8 + lc2;
            const float bi0 = bias[n], bi1 = bias[n + 1];
            if (PERM) {
                const int h = n >> 5, cc = n & 31;
                const __half2 v0 = __floats2half2_rn(acc[mt][nt][0] + bi0,
                                                     acc[mt][nt][1] + bi1);
                const __half2 v1 = __floats2half2_rn(acc[mt][nt][2] + bi0,
                                                     acc[mt][nt][3] + bi1);
                *reinterpret_cast<__half2*>(
                    &Cd[(((size_t)(bbA * H_SZ + h)) * S_SZ + ssA) * C_SZ + cc]) = v0;
                *reinterpret_cast<__half2*>(
                    &Cd[(((size_t)(bbB * H_SZ + h)) * S_SZ + ssB) * C_SZ + cc]) = v1;
            } else {
                float2 v0, v1;
                v0.x = acc[mt][nt][0] + bi0;
                v0.y = acc[mt][nt][1] + bi1;
                v1.x = acc[mt][nt][2] + bi0;
                v1.y = acc[mt][nt][3] + bi1;
                *reinterpret_cast<float2*>(&Cf[(size_t)mA * Ns + n]) = v0;
                *reinterpret_cast<float2*>(&Cf[(size_t)mB * Ns + n]) = v1;
            }
        }
    }
}

// ---------------- Stage 2b: sampling (dual-point half2) ----------------
__global__ __launch_bounds__(256) void sample_k(
    const float* __restrict__ proj, const float* __restrict__ refp,
    const __half* __restrict__ value, float* __restrict__ mixed)
{
    const int blk = blockIdx.x;        // b*Q + q
    const int b = blk / Q_SZ;
    const int h = threadIdx.x >> 5;
    const int lane = threadIdx.x & 31;

    const float rx = __ldg(&refp[blk * 4 + 0]);
    const float ry = __ldg(&refp[blk * 4 + 1]);
    const float rw = __ldg(&refp[blk * 4 + 2]);
    const float rh = __ldg(&refp[blk * 4 + 3]);

    float gx = 0.f, gy = 0.f, logit = -1e30f;
    if (lane < P_SZ) {
        const float ox = __ldg(&proj[(size_t)blk * PROJ_N + (h * P_SZ + lane) * 2]);
        const float oy = __ldg(&proj[(size_t)blk * PROJ_N + (h * P_SZ + lane) * 2 + 1]);
        logit = __ldg(&proj[(size_t)blk * PROJ_N + 192 + h * P_SZ + lane]);
        const float Wf = (lane < 4) ? 80.f : ((lane < 8) ? 40.f : 20.f);
        gx = (rx + ox * rw * 0.125f) * Wf - 0.5f;
        gy = (ry + oy * rh * 0.125f) * Wf - 0.5f;
    }
    float mx = logit;
    #pragma unroll
    for (int o = 16; o; o >>= 1) mx = fmaxf(mx, __shfl_xor_sync(0xffffffffu, mx, o));
    const float e = (lane < P_SZ) ? __expf(logit - mx) : 0.f;
    float sm = e;
    #pragma unroll
    for (int o = 16; o; o >>= 1) sm += __shfl_xor_sync(0xffffffffu, sm, o);
    const float w = e / sm;

    // lanes 0-15: even p, lanes 16-31: odd p; lane owns channel pair c2.
    const int c2 = (lane & 15) * 2;
    const int psel = lane >> 4;
    const __half* vbase = value + ((size_t)(b * H_SZ + h) * S_SZ) * C_SZ + c2;

    float accx = 0.f, accy = 0.f;
    #pragma unroll
    for (int pp = 0; pp < 6; pp++) {
        const int p = pp * 2 + psel;
        const float gxp = __shfl_sync(0xffffffffu, gx, p);
        const float gyp = __shfl_sync(0xffffffffu, gy, p);
        const float wp  = __shfl_sync(0xffffffffu, w,  p);
        const int Wl = (pp < 2) ? 80 : ((pp < 4) ? 40 : 20);
        const int st = (pp < 2) ? 0 : ((pp < 4) ? 6400 : 8000);
        const float x0f = floorf(gxp), y0f = floorf(gyp);
        const float wx1 = gxp - x0f, wx0 = 1.f - wx1;
        const float wy1 = gyp - y0f, wy0 = 1.f - wy1;
        const int x0 = (int)x0f, y0 = (int)y0f, x1 = x0 + 1, y1 = y0 + 1;
        const bool xv0 = (x0 >= 0) && (x0 < Wl);
        const bool xv1 = (x1 >= 0) && (x1 < Wl);
        const bool yv0 = (y0 >= 0) && (y0 < Wl);
        const bool yv1 = (y1 >= 0) && (y1 < Wl);
        const __half* lv = vbase + (size_t)st * C_SZ;

        float tx = 0.f, ty = 0.f;
        if (xv0 && yv0) {
            const float2 v = __half22float2(
                *reinterpret_cast<const __half2*>(lv + (size_t)(y0 * Wl + x0) * C_SZ));
            const float tw = wx0 * wy0;
            tx += tw * v.x; ty += tw * v.y;
        }
        if (xv1 && yv0) {
            const float2 v = __half22float2(
                *reinterpret_cast<const __half2*>(lv + (size_t)(y0 * Wl + x1) * C_SZ));
            const float tw = wx1 * wy0;
            tx += tw * v.x; ty += tw * v.y;
        }
        if (xv0 && yv1) {
            const float2 v = __half22float2(
                *reinterpret_cast<const __half2*>(lv + (size_t)(y1 * Wl + x0) * C_SZ));
            const float tw = wx0 * wy1;
            tx += tw * v.x; ty += tw * v.y;
        }
        if (xv1 && yv1) {
            const float2 v = __half22float2(
                *reinterpret_cast<const __half2*>(lv + (size_t)(y1 * Wl + x1) * C_SZ));
            const float tw = wx1 * wy1;
            tx += tw * v.x; ty += tw * v.y;
        }
        accx += wp * tx;
        accy += wp * ty;
    }
    accx += __shfl_xor_sync(0xffffffffu, accx, 16);
    accy += __shfl_xor_sync(0xffffffffu, accy, 16);
    if (lane < 16) {
        float2 o; o.x = accx; o.y = accy;
        *reinterpret_cast<float2*>(&mixed[(size_t)blk * 256 + h * C_SZ + c2]) = o;
    }
}

// ---------------------------------------------------------------------------
extern "C" void kernel_launch(void* const* d_in, const int* in_sizes, int n_in,
                              void* d_out, int out_size)
{
    const float* hidden = (const float*)d_in[0];
    const float* enc    = (const float*)d_in[1];
    const float* refp   = (const float*)d_in[2];
    const float* W_off  = (const float*)d_in[3];
    const float* b_off  = (const float*)d_in[4];
    const float* W_attn = (const float*)d_in[5];
    const float* b_attn = (const float*)d_in[6];
    const float* W_val  = (const float*)d_in[7];
    const float* b_val  = (const float*)d_in[8];
    const float* W_out  = (const float*)d_in[9];
    const float* b_out  = (const float*)d_in[10];
    float* out = (float*)d_out;

    float *mixed, *proj, *bproj;
    __half *value, *wh, *woh, *wph;
    cudaGetSymbolAddress((void**)&value, g_value);
    cudaGetSymbolAddress((void**)&mixed, g_mixed);
    cudaGetSymbolAddress((void**)&proj,  g_proj);
    cudaGetSymbolAddress((void**)&wh,    g_wh);
    cudaGetSymbolAddress((void**)&woh,   g_woh);
    cudaGetSymbolAddress((void**)&wph,   g_wph);
    cudaGetSymbolAddress((void**)&bproj, g_bproj);

    const int M1 = B_SZ * S_SZ;   // 268800
    const int M2 = B_SZ * Q_SZ;   // 9600

    wprep_k<<<256, 256>>>(W_val, wh);
    wprep_k<<<256, 256>>>(W_out, woh);
    pprep_k<<<PROJ_N, 256>>>(W_off, b_off, W_attn, b_attn, wph, bproj);

    // Stage 1: value projection (fp16 HMMA), fp16 permuted store
    {
        dim3 grid(2, M1 / 128);   // (2, 2100)
        gemm_hmma_k<true><<<grid, 256>>>(enc, wh, b_val, value, nullptr, 0);
    }
    // Stage 2a: offset/attn projection (fp16 HMMA, fp32 out, N=384)
    {
        dim3 grid(PROJ_N / 128, M2 / 128);   // (3, 75)
        gemm_hmma_k<false><<<grid, 256>>>(hidden, wph, bproj, nullptr, proj, PROJ_N);
    }
    // Stage 2b: sampling
    sample_k<<<M2, 256>>>(proj, refp, value, mixed);

    // Stage 3: output projection (fp16 HMMA, fp32 out, N=256)
    {
        dim3 grid(2, M2 / 128);   // (2, 75)
        gemm_hmma_k<false><<<grid, 256>>>(mixed, woh, b_out, nullptr, out, 256);
    }
}

// round 12
// speedup vs baseline: 3.1174x; 1.0094x over previous
#include <cuda_runtime.h>
#include <cuda_fp16.h>
#include <cstdint>
#include <cstddef>

// RT-DETR v2 deformable attention. B=32 Q=300 d=256 H=8 C=32 S=8400 P=12
// S1: value = enc@W_val+b (fp16 HMMA, B-persistent in smem) -> (B,H,S,C) fp16
// S2a: proj = hidden@[W_off|W_attn|pad384] (fp16 HMMA, fp32 out)
// S2b: softmax + bilinear sampling (warp/head, dual-point half2 lanes)
// S3: out = mixed@W_out+b (fp16 HMMA, fp32 out)
// R12: stage-1 keeps the 128x256 weight half resident in smem across ~14
//      m-tiles per CTA (kills per-chunk B LDG+STS, 96 of 392 L1 wavefronts).

#define B_SZ 32
#define Q_SZ 300
#define H_SZ 8
#define C_SZ 32
#define S_SZ 8400
#define P_SZ 12
#define PROJ_N 384
#define M_TILES 2100

__device__ __half g_value[(size_t)B_SZ * H_SZ * S_SZ * C_SZ];   // 137 MB
__device__ float  g_mixed[(size_t)B_SZ * Q_SZ * 256];
__device__ float  g_proj[(size_t)B_SZ * Q_SZ * PROJ_N];
__device__ __half g_wh[256 * 256];                               // W_val^T
__device__ __half g_woh[256 * 256];                              // W_out^T
__device__ __half g_wph[PROJ_N * 256];                           // [Woff|Wattn]^T
__device__ float  g_bproj[PROJ_N];

// ---------------- weight preps ----------------
__global__ void wprep_k(const float* __restrict__ W, __half* __restrict__ wh)
{
    const int n = blockIdx.x, k = threadIdx.x;
    wh[(size_t)n * 256 + k] = __float2half_rn(W[(size_t)k * 256 + n]);
}

__global__ void pprep_k(const float* __restrict__ W_off,
                        const float* __restrict__ b_off,
                        const float* __restrict__ W_attn,
                        const float* __restrict__ b_attn,
                        __half* __restrict__ wph, float* __restrict__ bp)
{
    const int n = blockIdx.x, k = threadIdx.x;   // n<384, k<256
    float v = 0.f, bv = 0.f;
    if (n < 192)      { v = W_off[(size_t)k * 192 + n];         bv = b_off[n]; }
    else if (n < 288) { v = W_attn[(size_t)k * 96 + (n - 192)]; bv = b_attn[n - 192]; }
    wph[(size_t)n * 256 + k] = __float2half_rn(v);
    if (k == 0) bp[n] = bv;
}

// ---------------- HMMA helpers ----------------
__device__ __forceinline__ uint32_t pkhf(float x, float y) {
    __half2 t = __floats2half2_rn(x, y);
    return *reinterpret_cast<uint32_t*>(&t);
}
__device__ __forceinline__ void mma16816(float* d, const uint32_t* a,
                                         const uint32_t* b) {
    asm volatile(
        "mma.sync.aligned.m16n8k16.row.col.f32.f16.f16.f32 "
        "{%0,%1,%2,%3}, {%4,%5,%6,%7}, {%8,%9}, {%0,%1,%2,%3};"
        : "+f"(d[0]), "+f"(d[1]), "+f"(d[2]), "+f"(d[3])
        : "r"(a[0]), "r"(a[1]), "r"(a[2]), "r"(a[3]), "r"(b[0]), "r"(b[1]));
}

#define PITCH 24        // A staging: 48B stride = 12 banks, conflict-free frags
#define PITCH_B 264     // persistent B: 528B stride = 132 = 4 mod 32 banks,
                        // frag banks = 4*(row%8)+(lane&3) -> conflict-free
#define S1_B_HALFS (128 * PITCH_B)                 // 33792
#define S1_A_HALFS (128 * PITCH)                   // 3072
#define S1_SMEM_BYTES ((S1_B_HALFS + 2 * S1_A_HALFS) * 2)   // 79872 B

// =================== Stage 1: persistent-B HMMA GEMM =====================
__global__ __launch_bounds__(256, 2) void gemm_s1_k(
    const float* __restrict__ A, const __half* __restrict__ Wh,
    const float* __restrict__ bias, __half* __restrict__ Cd)
{
    extern __shared__ uint16_t smem[];
    uint16_t* Bs  = smem;                         // [128][PITCH_B]
    uint16_t* As0 = smem + S1_B_HALFS;            // [128][PITCH]
    uint16_t* As1 = As0 + S1_A_HALFS;

    const int tid  = threadIdx.x;
    const int wid  = tid >> 5;
    const int lane = tid & 31;
    const int n0   = blockIdx.x * 128;
    const int m0w  = (wid & 3) * 32;
    const int n0w  = (wid >> 2) * 64;

    // ---- one-time B load: thread t -> row t>>1, col half (t&1)*128
    {
        const int row = tid >> 1, colb = (tid & 1) * 128;
        const __half* src = Wh + (size_t)(n0 + row) * 256 + colb;
        uint16_t* dst = Bs + row * PITCH_B + colb;
        #pragma unroll
        for (int kk = 0; kk < 16; kk++)
            *reinterpret_cast<uint4*>(dst + kk * 8) =
                *reinterpret_cast<const uint4*>(src + kk * 8);
    }
    __syncthreads();

    // A loader geometry
    const int arow0 = tid >> 2,          ac0 = (tid & 3) * 4;
    const int arow1 = (tid + 256) >> 2,  ac1 = ((tid + 256) & 3) * 4;
    const int lr  = lane >> 2;
    const int lc2 = (lane & 3) * 2;

    uint16_t* const Abuf[2] = {As0, As1};

#define STORE_A(DST) do {                                                   \
    {   uint16_t* p = (DST) + arow0 * PITCH + ac0;                          \
        *reinterpret_cast<uint32_t*>(p)     = pkhf(pa0.x, pa0.y);           \
        *reinterpret_cast<uint32_t*>(p + 2) = pkhf(pa0.z, pa0.w);           \
    }                                                                       \
    {   uint16_t* p = (DST) + arow1 * PITCH + ac1;                          \
        *reinterpret_cast<uint32_t*>(p)     = pkhf(pa1.x, pa1.y);           \
        *reinterpret_cast<uint32_t*>(p + 2) = pkhf(pa1.z, pa1.w);           \
    }                                                                       \
} while (0)

    #pragma unroll 1
    for (int mtile = blockIdx.y; mtile < M_TILES; mtile += gridDim.y) {
        const int m0 = mtile * 128;
        float acc[2][8][4] = {};
        float4 pa0, pa1;

        pa0 = *reinterpret_cast<const float4*>(&A[(size_t)(m0 + arow0) * 256 + ac0]);
        pa1 = *reinterpret_cast<const float4*>(&A[(size_t)(m0 + arow1) * 256 + ac1]);
        STORE_A(As0);
        __syncthreads();

        #pragma unroll 1
        for (int c = 0; c < 16; ++c) {
            const int buf = c & 1;
            if (c < 15) {
                const int k0 = (c + 1) * 16;
                pa0 = *reinterpret_cast<const float4*>(&A[(size_t)(m0 + arow0) * 256 + k0 + ac0]);
                pa1 = *reinterpret_cast<const float4*>(&A[(size_t)(m0 + arow1) * 256 + k0 + ac1]);
            }

            uint32_t ah[2][4], bh[8][2];
            #pragma unroll
            for (int mt = 0; mt < 2; mt++) {
                const int r = m0w + mt * 16 + lr;
                const uint16_t* ab = Abuf[buf];
                ah[mt][0] = *reinterpret_cast<const uint32_t*>(&ab[r * PITCH + lc2]);
                ah[mt][1] = *reinterpret_cast<const uint32_t*>(&ab[(r + 8) * PITCH + lc2]);
                ah[mt][2] = *reinterpret_cast<const uint32_t*>(&ab[r * PITCH + lc2 + 8]);
                ah[mt][3] = *reinterpret_cast<const uint32_t*>(&ab[(r + 8) * PITCH + lc2 + 8]);
            }
            const int kb = c * 16;
            #pragma unroll
            for (int nt = 0; nt < 8; nt++) {
                const int r = n0w + nt * 8 + lr;
                bh[nt][0] = *reinterpret_cast<const uint32_t*>(&Bs[r * PITCH_B + kb + lc2]);
                bh[nt][1] = *reinterpret_cast<const uint32_t*>(&Bs[r * PITCH_B + kb + lc2 + 8]);
            }

            #pragma unroll
            for (int mt = 0; mt < 2; mt++)
                #pragma unroll
                for (int nt = 0; nt < 8; nt++)
                    mma16816(acc[mt][nt], ah[mt], bh[nt]);

            if (c < 15) {
                STORE_A(Abuf[buf ^ 1]);
                __syncthreads();
            }
        }

        // epilogue: permuted fp16 store (B,H,S,C) with bias
        #pragma unroll
        for (int mt = 0; mt < 2; mt++) {
            const int mA = m0 + m0w + mt * 16 + lr;
            const int mB = mA + 8;
            const int bbA = mA / S_SZ, ssA = mA % S_SZ;
            const int bbB = mB / S_SZ, ssB = mB % S_SZ;
            #pragma unroll
            for (int nt = 0; nt < 8; nt++) {
                const int n = n0 + n0w + nt * 8 + lc2;
                const int h = n >> 5, cc = n & 31;
                const float bi0 = bias[n], bi1 = bias[n + 1];
                const __half2 v0 = __floats2half2_rn(acc[mt][nt][0] + bi0,
                                                     acc[mt][nt][1] + bi1);
                const __half2 v1 = __floats2half2_rn(acc[mt][nt][2] + bi0,
                                                     acc[mt][nt][3] + bi1);
                *reinterpret_cast<__half2*>(
                    &Cd[(((size_t)(bbA * H_SZ + h)) * S_SZ + ssA) * C_SZ + cc]) = v0;
                *reinterpret_cast<__half2*>(
                    &Cd[(((size_t)(bbB * H_SZ + h)) * S_SZ + ssB) * C_SZ + cc]) = v1;
            }
        }
        // next m-tile's STORE_A(As0) is safe: As0 last read at c=14, all
        // warps passed the c=14 sync; the sync after STORE_A(As0) orders
        // c=15 reads of As1 before its overwrite at c=0.
    }
#undef STORE_A
}

// =================== small GEMM (proj / out): fp32 out ===================
__global__ __launch_bounds__(256) void gemm_hmma2_k(
    const float* __restrict__ A, const __half* __restrict__ Wh,
    const float* __restrict__ bias, float* __restrict__ Cf, int Ns)
{
    __shared__ uint16_t sA[2][128 * PITCH];
    __shared__ uint16_t sB[2][128 * PITCH];

    const int tid  = threadIdx.x;
    const int wid  = tid >> 5;
    const int lane = tid & 31;
    const int m0 = blockIdx.y * 128;
    const int n0 = blockIdx.x * 128;
    const int m0w = (wid & 3) * 32;
    const int n0w = (wid >> 2) * 64;

    const int arow0 = tid >> 2,          ac0 = (tid & 3) * 4;
    const int arow1 = (tid + 256) >> 2,  ac1 = ((tid + 256) & 3) * 4;
    const int brow  = tid >> 1,          boff = (tid & 1) * 8;

    float acc[2][8][4] = {};
    float4 pa0, pa1;
    uint4  pbh;

    pa0 = *reinterpret_cast<const float4*>(&A[(size_t)(m0 + arow0) * 256 + ac0]);
    pa1 = *reinterpret_cast<const float4*>(&A[(size_t)(m0 + arow1) * 256 + ac1]);
    pbh = *reinterpret_cast<const uint4*>(&Wh[(size_t)(n0 + brow) * 256 + boff]);

#define STORE_CHUNK(BUF) do {                                              \
    {   uint16_t* p = &sA[BUF][arow0 * PITCH + ac0];                       \
        *reinterpret_cast<uint32_t*>(p)     = pkhf(pa0.x, pa0.y);          \
        *reinterpret_cast<uint32_t*>(p + 2) = pkhf(pa0.z, pa0.w);          \
    }                                                                      \
    {   uint16_t* p = &sA[BUF][arow1 * PITCH + ac1];                       \
        *reinterpret_cast<uint32_t*>(p)     = pkhf(pa1.x, pa1.y);          \
        *reinterpret_cast<uint32_t*>(p + 2) = pkhf(pa1.z, pa1.w);          \
    }                                                                      \
    {   uint16_t* p = &sB[BUF][brow * PITCH + boff];                       \
        *reinterpret_cast<uint32_t*>(p)     = pbh.x;                       \
        *reinterpret_cast<uint32_t*>(p + 2) = pbh.y;                       \
        *reinterpret_cast<uint32_t*>(p + 4) = pbh.z;                       \
        *reinterpret_cast<uint32_t*>(p + 6) = pbh.w;                       \
    }                                                                      \
} while (0)

    STORE_CHUNK(0);
    __syncthreads();

    const int lr  = lane >> 2;
    const int lc2 = (lane & 3) * 2;

    #pragma unroll 1
    for (int c = 0; c < 16; ++c) {
        const int buf = c & 1;
        if (c < 15) {
            const int k0 = (c + 1) * 16;
            pa0 = *reinterpret_cast<const float4*>(&A[(size_t)(m0 + arow0) * 256 + k0 + ac0]);
            pa1 = *reinterpret_cast<const float4*>(&A[(size_t)(m0 + arow1) * 256 + k0 + ac1]);
            pbh = *reinterpret_cast<const uint4*>(&Wh[(size_t)(n0 + brow) * 256 + k0 + boff]);
        }

        uint32_t ah[2][4], bh[8][2];
        #pragma unroll
        for (int mt = 0; mt < 2; mt++) {
            const int r = m0w + mt * 16 + lr;
            ah[mt][0] = *reinterpret_cast<const uint32_t*>(&sA[buf][r * PITCH + lc2]);
            ah[mt][1] = *reinterpret_cast<const uint32_t*>(&sA[buf][(r + 8) * PITCH + lc2]);
            ah[mt][2] = *reinterpret_cast<const uint32_t*>(&sA[buf][r * PITCH + lc2 + 8]);
            ah[mt][3] = *reinterpret_cast<const uint32_t*>(&sA[buf][(r + 8) * PITCH + lc2 + 8]);
        }
        #pragma unroll
        for (int nt = 0; nt < 8; nt++) {
            const int r = n0w + nt * 8 + lr;
            bh[nt][0] = *reinterpret_cast<const uint32_t*>(&sB[buf][r * PITCH + lc2]);
            bh[nt][1] = *reinterpret_cast<const uint32_t*>(&sB[buf][r * PITCH + lc2 + 8]);
        }

        #pragma unroll
        for (int mt = 0; mt < 2; mt++)
            #pragma unroll
            for (int nt = 0; nt < 8; nt++)
                mma16816(acc[mt][nt], ah[mt], bh[nt]);

        if (c < 15) {
            STORE_CHUNK(buf ^ 1);
            __syncthreads();
        }
    }
#undef STORE_CHUNK

    #pragma unroll
    for (int mt = 0; mt < 2; mt++) {
        const int mA = m0 + m0w + mt * 16 + lr;
        const int mB = mA + 8;
        #pragma unroll
        for (int nt = 0; nt < 8; nt++) {
            const int n = n0 + n0w + nt * 8 + lc2;
            const float bi0 = bias[n], bi1 = bias[n + 1];
            float2 v0, v1;
            v0.x = acc[mt][nt][0] + bi0;
            v0.y = acc[mt][nt][1] + bi1;
            v1.x = acc[mt][nt][2] + bi0;
            v1.y = acc[mt][nt][3] + bi1;
            *reinterpret_cast<float2*>(&Cf[(size_t)mA * Ns + n]) = v0;
            *reinterpret_cast<float2*>(&Cf[(size_t)mB * Ns + n]) = v1;
        }
    }
}

// ---------------- Stage 2b: sampling (dual-point half2) ----------------
__global__ __launch_bounds__(256) void sample_k(
    const float* __restrict__ proj, const float* __restrict__ refp,
    const __half* __restrict__ value, float* __restrict__ mixed)
{
    const int blk = blockIdx.x;        // b*Q + q
    const int b = blk / Q_SZ;
    const int h = threadIdx.x >> 5;
    const int lane = threadIdx.x & 31;

    const float rx = __ldg(&refp[blk * 4 + 0]);
    const float ry = __ldg(&refp[blk * 4 + 1]);
    const float rw = __ldg(&refp[blk * 4 + 2]);
    const float rh = __ldg(&refp[blk * 4 + 3]);

    float gx = 0.f, gy = 0.f, logit = -1e30f;
    if (lane < P_SZ) {
        const float ox = __ldg(&proj[(size_t)blk * PROJ_N + (h * P_SZ + lane) * 2]);
        const float oy = __ldg(&proj[(size_t)blk * PROJ_N + (h * P_SZ + lane) * 2 + 1]);
        logit = __ldg(&proj[(size_t)blk * PROJ_N + 192 + h * P_SZ + lane]);
        const float Wf = (lane < 4) ? 80.f : ((lane < 8) ? 40.f : 20.f);
        gx = (rx + ox * rw * 0.125f) * Wf - 0.5f;
        gy = (ry + oy * rh * 0.125f) * Wf - 0.5f;
    }
    float mx = logit;
    #pragma unroll
    for (int o = 16; o; o >>= 1) mx = fmaxf(mx, __shfl_xor_sync(0xffffffffu, mx, o));
    const float e = (lane < P_SZ) ? __expf(logit - mx) : 0.f;
    float sm = e;
    #pragma unroll
    for (int o = 16; o; o >>= 1) sm += __shfl_xor_sync(0xffffffffu, sm, o);
    const float w = e / sm;

    // lanes 0-15: even p, lanes 16-31: odd p; lane owns channel pair c2.
    const int c2 = (lane & 15) * 2;
    const int psel = lane >> 4;
    const __half* vbase = value + ((size_t)(b * H_SZ + h) * S_SZ) * C_SZ + c2;

    float accx = 0.f, accy = 0.f;
    #pragma unroll
    for (int pp = 0; pp < 6; pp++) {
        const int p = pp * 2 + psel;
        const float gxp = __shfl_sync(0xffffffffu, gx, p);
        const float gyp = __shfl_sync(0xffffffffu, gy, p);
        const float wp  = __shfl_sync(0xffffffffu, w,  p);
        const int Wl = (pp < 2) ? 80 : ((pp < 4) ? 40 : 20);
        const int st = (pp < 2) ? 0 : ((pp < 4) ? 6400 : 8000);
        const float x0f = floorf(gxp), y0f = floorf(gyp);
        const float wx1 = gxp - x0f, wx0 = 1.f - wx1;
        const float wy1 = gyp - y0f, wy0 = 1.f - wy1;
        const int x0 = (int)x0f, y0 = (int)y0f, x1 = x0 + 1, y1 = y0 + 1;
        const bool xv0 = (x0 >= 0) && (x0 < Wl);
        const bool xv1 = (x1 >= 0) && (x1 < Wl);
        const bool yv0 = (y0 >= 0) && (y0 < Wl);
        const bool yv1 = (y1 >= 0) && (y1 < Wl);
        const __half* lv = vbase + (size_t)st * C_SZ;

        float tx = 0.f, ty = 0.f;
        if (xv0 && yv0) {
            const float2 v = __half22float2(
                *reinterpret_cast<const __half2*>(lv + (size_t)(y0 * Wl + x0) * C_SZ));
            const float tw = wx0 * wy0;
            tx += tw * v.x; ty += tw * v.y;
        }
        if (xv1 && yv0) {
            const float2 v = __half22float2(
                *reinterpret_cast<const __half2*>(lv + (size_t)(y0 * Wl + x1) * C_SZ));
            const float tw = wx1 * wy0;
            tx += tw * v.x; ty += tw * v.y;
        }
        if (xv0 && yv1) {
            const float2 v = __half22float2(
                *reinterpret_cast<const __half2*>(lv + (size_t)(y1 * Wl + x0) * C_SZ));
            const float tw = wx0 * wy1;
            tx += tw * v.x; ty += tw * v.y;
        }
        if (xv1 && yv1) {
            const float2 v = __half22float2(
                *reinterpret_cast<const __half2*>(lv + (size_t)(y1 * Wl + x1) * C_SZ));
            const float tw = wx1 * wy1;
            tx += tw * v.x; ty += tw * v.y;
        }
        accx += wp * tx;
        accy += wp * ty;
    }
    accx += __shfl_xor_sync(0xffffffffu, accx, 16);
    accy += __shfl_xor_sync(0xffffffffu, accy, 16);
    if (lane < 16) {
        float2 o; o.x = accx; o.y = accy;
        *reinterpret_cast<float2*>(&mixed[(size_t)blk * 256 + h * C_SZ + c2]) = o;
    }
}

// ---------------------------------------------------------------------------
extern "C" void kernel_launch(void* const* d_in, const int* in_sizes, int n_in,
                              void* d_out, int out_size)
{
    const float* hidden = (const float*)d_in[0];
    const float* enc    = (const float*)d_in[1];
    const float* refp   = (const float*)d_in[2];
    const float* W_off  = (const float*)d_in[3];
    const float* b_off  = (const float*)d_in[4];
    const float* W_attn = (const float*)d_in[5];
    const float* b_attn = (const float*)d_in[6];
    const float* W_val  = (const float*)d_in[7];
    const float* b_val  = (const float*)d_in[8];
    const float* W_out  = (const float*)d_in[9];
    const float* b_out  = (const float*)d_in[10];
    float* out = (float*)d_out;

    float *mixed, *proj, *bproj;
    __half *value, *wh, *woh, *wph;
    cudaGetSymbolAddress((void**)&value, g_value);
    cudaGetSymbolAddress((void**)&mixed, g_mixed);
    cudaGetSymbolAddress((void**)&proj,  g_proj);
    cudaGetSymbolAddress((void**)&wh,    g_wh);
    cudaGetSymbolAddress((void**)&woh,   g_woh);
    cudaGetSymbolAddress((void**)&wph,   g_wph);
    cudaGetSymbolAddress((void**)&bproj, g_bproj);

    const int M2 = B_SZ * Q_SZ;   // 9600

    cudaFuncSetAttribute(gemm_s1_k,
                         cudaFuncAttributeMaxDynamicSharedMemorySize,
                         S1_SMEM_BYTES);

    wprep_k<<<256, 256>>>(W_val, wh);
    wprep_k<<<256, 256>>>(W_out, woh);
    pprep_k<<<PROJ_N, 256>>>(W_off, b_off, W_attn, b_attn, wph, bproj);

    // Stage 1: value projection, persistent-B (2 n-tiles x 148 CTAs)
    {
        dim3 grid(2, 148);
        gemm_s1_k<<<grid, 256, S1_SMEM_BYTES>>>(enc, wh, b_val, value);
    }
    // Stage 2a: offset/attn projection (fp16 HMMA, fp32 out, N=384)
    {
        dim3 grid(PROJ_N / 128, M2 / 128);   // (3, 75)
        gemm_hmma2_k<<<grid, 256>>>(hidden, wph, bproj, proj, PROJ_N);
    }
    // Stage 2b: sampling
    sample_k<<<M2, 256>>>(proj, refp, value, mixed);

    // Stage 3: output projection (fp16 HMMA, fp32 out, N=256)
    {
        dim3 grid(2, M2 / 128);   // (2, 75)
        gemm_hmma2_k<<<grid, 256>>>(mixed, woh, b_out, out, 256);
    }
}